// round 1
// baseline (speedup 1.0000x reference)
#include <cuda_runtime.h>
#include <cstdint>

#define NN    100000
#define EE    1600000
#define HID   128
#define INDIM 20
#define NREL  3
#define NTYPE 4
#define LN_EPS 1e-5f

// ---------------- device scratch (no allocs allowed) ----------------
static __device__ float g_x[(size_t)NN * HID];          // node features (51.2 MB)
static __device__ float g_y[(size_t)NN * NREL * HID];   // per-relation transformed feats [n][r][c] (153.6 MB)
static __device__ float g_h[(size_t)NN * HID];          // pre-LN accumulator (51.2 MB)
static __device__ float g_deg[NN];
static __device__ float g_deginv[NN];
static __device__ int   g_tlist[(size_t)NTYPE * NN];
static __device__ int   g_tcount[NTYPE];
static __device__ float g_pool[HID];

// ---------------- init / bucketing / degree ----------------
__global__ void k_init() {
    int i = blockIdx.x * blockDim.x + threadIdx.x;
    if (i < NN) g_deg[i] = 0.f;
    if (i < NTYPE) g_tcount[i] = 0;
    if (i < HID) g_pool[i] = 0.f;
}

__global__ void k_bucket(const int* __restrict__ ntype) {
    int i = blockIdx.x * blockDim.x + threadIdx.x;
    if (i >= NN) return;
    int t = ntype[i];
    int pos = atomicAdd(&g_tcount[t], 1);
    g_tlist[(size_t)t * NN + pos] = i;
}

__global__ void k_deg(const int* __restrict__ dst) {
    int e = blockIdx.x * blockDim.x + threadIdx.x;
    if (e >= EE) return;
    atomicAdd(&g_deg[dst[e]], 1.0f);
}

__global__ void k_deginv() {
    int i = blockIdx.x * blockDim.x + threadIdx.x;
    if (i >= NN) return;
    g_deginv[i] = 1.0f / fmaxf(g_deg[i], 1.0f);
}

// ---------------- type-specific encoder ----------------
// grid (ceil(N/128), 4); 256 threads; blocks beyond this type's node count exit.
// smem: W1[20*128] + raw[128*21] + h1[128*128] (layout [k][n]) + W2[128*128]
#define ENC_SMEM ((2560 + 2688 + 16384 + 16384) * 4)

__global__ void __launch_bounds__(256, 1)
k_encoder(const int* __restrict__ z, const float* __restrict__ sd,
          const float* __restrict__ dfp, const float* __restrict__ cond,
          const float* __restrict__ mult, const float* __restrict__ zemb,
          const float* __restrict__ W1, const float* __restrict__ b1,
          const float* __restrict__ W2, const float* __restrict__ b2) {
    int t = blockIdx.y;
    int cnt = g_tcount[t];
    int start = blockIdx.x * 128;
    if (start >= cnt) return;

    extern __shared__ float sm[];
    float* W1s  = sm;            // [20][128]
    float* raws = W1s + 2560;    // [128 nodes][stride 21]
    float* h1s  = raws + 2688;   // [128 k][128 n]
    float* W2s  = h1s + 16384;   // [128 k][128 c]
    __shared__ int nl[128];

    int tid = threadIdx.x;
    if (tid < 128) {
        int idx = start + tid;
        nl[tid] = g_tlist[(size_t)t * NN + (idx < cnt ? idx : cnt - 1)];
    }
    for (int i = tid; i < 640; i += 256)
        *(float4*)&W1s[i * 4] = *(const float4*)&W1[(size_t)t * 2560 + i * 4];
    for (int i = tid; i < 4096; i += 256)
        *(float4*)&W2s[i * 4] = *(const float4*)&W2[(size_t)t * 16384 + i * 4];
    __syncthreads();

    // build raw features [z_embed(16) | sd df cond mult]
    for (int i = tid; i < 128 * INDIM; i += 256) {
        int n = i / INDIM, k = i % INDIM;
        int node = nl[n];
        float v;
        if (k < 16)       v = zemb[(size_t)z[node] * 16 + k];
        else if (k == 16) v = sd[node];
        else if (k == 17) v = dfp[node];
        else if (k == 18) v = cond[node];
        else              v = mult[node];
        raws[n * 21 + k] = v;
    }
    __syncthreads();

    // stage 1: h1[c][n] = relu(raw[n] . W1[:,c] + b1[c]); per-thread n fixed, c varies
    {
        int n = tid & 127;
        float r20[INDIM];
#pragma unroll
        for (int k = 0; k < INDIM; k++) r20[k] = raws[n * 21 + k];
        int chalf = tid >> 7;
        for (int p = 0; p < 64; p++) {
            int c = chalf + p * 2;
            float s = b1[t * HID + c];
#pragma unroll
            for (int k = 0; k < INDIM; k++) s += r20[k] * W1s[k * 128 + c];
            h1s[c * 128 + n] = fmaxf(s, 0.f);
        }
    }
    __syncthreads();

    // stage 2: out = h1 @ W2 + b2, 8x8 register tile
    int tx = tid & 15, ty = tid >> 4;
    float acc[8][8] = {};
    for (int k = 0; k < 128; k++) {
        float4 a0 = *(const float4*)&h1s[k * 128 + ty * 8];
        float4 a1 = *(const float4*)&h1s[k * 128 + ty * 8 + 4];
        float4 w0 = *(const float4*)&W2s[k * 128 + tx * 8];
        float4 w1 = *(const float4*)&W2s[k * 128 + tx * 8 + 4];
        float av[8] = {a0.x, a0.y, a0.z, a0.w, a1.x, a1.y, a1.z, a1.w};
        float wv[8] = {w0.x, w0.y, w0.z, w0.w, w1.x, w1.y, w1.z, w1.w};
#pragma unroll
        for (int i = 0; i < 8; i++)
#pragma unroll
            for (int j = 0; j < 8; j++) acc[i][j] += av[i] * wv[j];
    }
    int c0 = tx * 8;
    float bb[8];
#pragma unroll
    for (int j = 0; j < 8; j++) bb[j] = b2[t * HID + c0 + j];
    for (int i = 0; i < 8; i++) {
        int gi = start + ty * 8 + i;
        if (gi >= cnt) break;
        int node = nl[ty * 8 + i];
        float4 o0 = make_float4(acc[i][0] + bb[0], acc[i][1] + bb[1],
                                acc[i][2] + bb[2], acc[i][3] + bb[3]);
        float4 o1 = make_float4(acc[i][4] + bb[4], acc[i][5] + bb[5],
                                acc[i][6] + bb[6], acc[i][7] + bb[7]);
        *(float4*)&g_x[(size_t)node * HID + c0]     = o0;
        *(float4*)&g_x[(size_t)node * HID + c0 + 4] = o1;
    }
}

// ---------------- fused dense GEMM: [N,128] @ [128,512] ----------------
// grid (ceil(N/128), 4). col-tile 0..2 -> y (relation r), col-tile 3 -> h = x@lin + b
#define GEMM_SMEM (2 * 128 * 128 * 4)

__global__ void __launch_bounds__(256, 1)
k_gemm(const float* __restrict__ relW, const float* __restrict__ linW,
       const float* __restrict__ linb) {
    extern __shared__ float sm[];
    float* As = sm;                 // [k][row] (transposed)
    float* Ws = sm + 128 * 128;     // [k][col]
    int jt = blockIdx.y;
    int rowBase = blockIdx.x * 128;
    int tid = threadIdx.x;

    for (int i = tid; i < 128 * 32; i += 256) {
        int row = i & 127;
        int c4 = i >> 7;
        int srcRow = rowBase + row;
        if (srcRow >= NN) srcRow = NN - 1;
        float4 v = *(const float4*)&g_x[(size_t)srcRow * HID + c4 * 4];
        As[(c4 * 4 + 0) * 128 + row] = v.x;
        As[(c4 * 4 + 1) * 128 + row] = v.y;
        As[(c4 * 4 + 2) * 128 + row] = v.z;
        As[(c4 * 4 + 3) * 128 + row] = v.w;
    }
    const float* Wsrc = (jt < 3) ? (relW + (size_t)jt * HID * HID) : linW;
    for (int i = tid; i < 128 * 32; i += 256) {
        int k = i >> 5, c4 = i & 31;
        *(float4*)&Ws[k * 128 + c4 * 4] = *(const float4*)&Wsrc[k * 128 + c4 * 4];
    }
    __syncthreads();

    int tx = tid & 15, ty = tid >> 4;
    const float* ap = &As[ty * 8];
    const float* wp = &Ws[tx * 8];
    float acc[8][8] = {};
#pragma unroll 4
    for (int k = 0; k < 128; k++) {
        float4 a0 = *(const float4*)(ap + k * 128);
        float4 a1 = *(const float4*)(ap + k * 128 + 4);
        float4 w0 = *(const float4*)(wp + k * 128);
        float4 w1 = *(const float4*)(wp + k * 128 + 4);
        float av[8] = {a0.x, a0.y, a0.z, a0.w, a1.x, a1.y, a1.z, a1.w};
        float wv[8] = {w0.x, w0.y, w0.z, w0.w, w1.x, w1.y, w1.z, w1.w};
#pragma unroll
        for (int i = 0; i < 8; i++)
#pragma unroll
            for (int j = 0; j < 8; j++) acc[i][j] += av[i] * wv[j];
    }

    if (jt < 3) {
        for (int i = 0; i < 8; i++) {
            int row = rowBase + ty * 8 + i;
            if (row >= NN) break;
            float* dp = &g_y[(size_t)row * (NREL * HID) + jt * HID + tx * 8];
            *(float4*)dp       = make_float4(acc[i][0], acc[i][1], acc[i][2], acc[i][3]);
            *(float4*)(dp + 4) = make_float4(acc[i][4], acc[i][5], acc[i][6], acc[i][7]);
        }
    } else {
        int c0 = tx * 8;
        float bb[8];
#pragma unroll
        for (int j = 0; j < 8; j++) bb[j] = linb[c0 + j];
        for (int i = 0; i < 8; i++) {
            int row = rowBase + ty * 8 + i;
            if (row >= NN) break;
            float* dp = &g_h[(size_t)row * HID + c0];
            *(float4*)dp       = make_float4(acc[i][0] + bb[0], acc[i][1] + bb[1],
                                             acc[i][2] + bb[2], acc[i][3] + bb[3]);
            *(float4*)(dp + 4) = make_float4(acc[i][4] + bb[4], acc[i][5] + bb[5],
                                             acc[i][6] + bb[6], acc[i][7] + bb[7]);
        }
    }
}

// ---------------- sparse scatter: h[dst] += y[src, et] * deginv[dst] ----------------
__global__ void k_edge(const int* __restrict__ src, const int* __restrict__ dst,
                       const int* __restrict__ etyp) {
    int w = (blockIdx.x * blockDim.x + threadIdx.x) >> 5;
    if (w >= EE) return;
    int lane = threadIdx.x & 31;
    int s = src[w];
    int d = dst[w];
    int r = etyp[w];
    float sc = g_deginv[d];
    float4 v = *(const float4*)&g_y[(size_t)s * (NREL * HID) + r * HID + lane * 4];
    float4 o = make_float4(v.x * sc, v.y * sc, v.z * sc, v.w * sc);
    float* p = &g_h[(size_t)d * HID + lane * 4];
    asm volatile("red.global.add.v4.f32 [%0], {%1,%2,%3,%4};"
                 :: "l"(p), "f"(o.x), "f"(o.y), "f"(o.z), "f"(o.w)
                 : "memory");
}

// ---------------- LayerNorm: x = (h-mu)/sqrt(var+eps)*g + b ----------------
__global__ void k_ln(const float* __restrict__ g, const float* __restrict__ b) {
    int warp = threadIdx.x >> 5, lane = threadIdx.x & 31;
    int node = blockIdx.x * 8 + warp;
    if (node >= NN) return;
    float4 v = *(const float4*)&g_h[(size_t)node * HID + lane * 4];
    float s = v.x + v.y + v.z + v.w;
#pragma unroll
    for (int o = 16; o; o >>= 1) s += __shfl_xor_sync(0xFFFFFFFFu, s, o);
    float mu = s * (1.0f / HID);
    float dx = v.x - mu, dy = v.y - mu, dz = v.z - mu, dw = v.w - mu;
    float s2 = dx * dx + dy * dy + dz * dz + dw * dw;
#pragma unroll
    for (int o = 16; o; o >>= 1) s2 += __shfl_xor_sync(0xFFFFFFFFu, s2, o);
    float rs = rsqrtf(s2 * (1.0f / HID) + LN_EPS);
    int c = lane * 4;
    float4 gg = *(const float4*)&g[c];
    float4 bb = *(const float4*)&b[c];
    float4 o = make_float4(dx * rs * gg.x + bb.x, dy * rs * gg.y + bb.y,
                           dz * rs * gg.z + bb.z, dw * rs * gg.w + bb.w);
    *(float4*)&g_x[(size_t)node * HID + c] = o;
}

// ---------------- pooling + regressor ----------------
__global__ void k_pool() {
    int c = threadIdx.x;                 // 128 threads
    int base = blockIdx.x * 256;
    float s = 0.f;
    for (int n = 0; n < 256; n++) {
        int node = base + n;
        if (node >= NN) break;
        s += g_x[(size_t)node * HID + c];
    }
    atomicAdd(&g_pool[c], s);
}

__global__ void k_final(const float* __restrict__ regW, const float* __restrict__ regb,
                        float* __restrict__ out) {
    int c = threadIdx.x;
    __shared__ float red[HID];
    red[c] = g_pool[c] * (1.0f / NN) * regW[c];
    __syncthreads();
    for (int s = 64; s; s >>= 1) {
        if (c < s) red[c] += red[c + s];
        __syncthreads();
    }
    if (c == 0) out[0] = red[0] + regb[0];
}

// ---------------- launch ----------------
extern "C" void kernel_launch(void* const* d_in, const int* in_sizes, int n_in,
                              void* d_out, int out_size) {
    const int*   z     = (const int*)d_in[0];
    const float* sd    = (const float*)d_in[1];
    const float* dfp   = (const float*)d_in[2];
    const float* cond  = (const float*)d_in[3];
    const float* mult  = (const float*)d_in[4];
    const int*   ntype = (const int*)d_in[5];
    const int*   eidx  = (const int*)d_in[6];   // [2,E]: src = eidx, dst = eidx+E
    const int*   etyp  = (const int*)d_in[7];
    const float* zemb  = (const float*)d_in[8];
    const float* eW1   = (const float*)d_in[9];
    const float* eb1   = (const float*)d_in[10];
    const float* eW2   = (const float*)d_in[11];
    const float* eb2   = (const float*)d_in[12];
    const float* linW  = (const float*)d_in[13];
    const float* linb  = (const float*)d_in[14];
    const float* relW  = (const float*)d_in[15];
    const float* lng   = (const float*)d_in[16];
    const float* lnb   = (const float*)d_in[17];
    const float* regW  = (const float*)d_in[18];
    const float* regb  = (const float*)d_in[19];
    float* out = (float*)d_out;

    cudaFuncSetAttribute(k_gemm, cudaFuncAttributeMaxDynamicSharedMemorySize, GEMM_SMEM);
    cudaFuncSetAttribute(k_encoder, cudaFuncAttributeMaxDynamicSharedMemorySize, ENC_SMEM);

    const int rowBlocks = (NN + 127) / 128;   // 782

    k_init<<<(NN + 255) / 256, 256>>>();
    k_bucket<<<(NN + 255) / 256, 256>>>(ntype);
    k_deg<<<(EE + 255) / 256, 256>>>(eidx + EE);
    k_deginv<<<(NN + 255) / 256, 256>>>();
    k_encoder<<<dim3(rowBlocks, NTYPE), 256, ENC_SMEM>>>(z, sd, dfp, cond, mult,
                                                         zemb, eW1, eb1, eW2, eb2);
    for (int l = 0; l < 2; l++) {
        k_gemm<<<dim3(rowBlocks, 4), 256, GEMM_SMEM>>>(
            relW + (size_t)l * NREL * HID * HID,
            linW + (size_t)l * HID * HID,
            linb + l * HID);
        k_edge<<<EE / 8, 256>>>(eidx, eidx + EE, etyp);
        k_ln<<<NN / 8, 256>>>(lng + l * HID, lnb + l * HID);
    }
    k_pool<<<(NN + 255) / 256, 128>>>();
    k_final<<<1, 128>>>(regW, regb, out);
}

// round 3
// speedup vs baseline: 1.3370x; 1.3370x over previous
#include <cuda_runtime.h>
#include <cuda_bf16.h>
#include <cstdint>

#define NN    100000
#define NPAD  100096
#define EE    1600000
#define HID   128
#define INDIM 20
#define NREL  3
#define NTYPE 4
#define LN_EPS 1e-5f

// ---------------- device scratch (no allocs allowed) ----------------
static __device__ float g_x[(size_t)NN * HID];          // node features fp32 (pool input)
static __device__ float g_y[(size_t)NN * NREL * HID];   // per-relation transformed feats [n][r][c]
static __device__ float g_h[(size_t)NN * HID];          // pre-LN accumulator
static __device__ __nv_bfloat16 g_xh[(size_t)NPAD * HID];  // x hi (bf16); pad rows stay 0
static __device__ __nv_bfloat16 g_xl[(size_t)NPAD * HID];  // x lo residual
static __device__ __nv_bfloat16 g_Bh[2 * 512 * 128];       // weights B[n][k] hi, per layer
static __device__ __nv_bfloat16 g_Bl[2 * 512 * 128];       // weights lo
static __device__ float g_deg[NN];
static __device__ float g_deginv[NN];
static __device__ int   g_tlist[(size_t)NTYPE * NN];
static __device__ int   g_tcount[NTYPE];
static __device__ float g_pool[HID];

// ---------------- split helper ----------------
__device__ __forceinline__ void split2(float a, float b, __nv_bfloat162* hi, __nv_bfloat162* lo) {
    __nv_bfloat16 ha = __float2bfloat16(a), hb = __float2bfloat16(b);
    *hi = __nv_bfloat162(ha, hb);
    *lo = __nv_bfloat162(__float2bfloat16(a - __bfloat162float(ha)),
                         __float2bfloat16(b - __bfloat162float(hb)));
}

// ---------------- init / bucketing / degree ----------------
__global__ void k_init() {
    int i = blockIdx.x * blockDim.x + threadIdx.x;
    if (i < NN) g_deg[i] = 0.f;
    if (i < NTYPE) g_tcount[i] = 0;
    if (i < HID) g_pool[i] = 0.f;
}

__global__ void k_bucket(const int* __restrict__ ntype) {
    int i = blockIdx.x * blockDim.x + threadIdx.x;
    if (i >= NN) return;
    int t = ntype[i];
    int pos = atomicAdd(&g_tcount[t], 1);
    g_tlist[(size_t)t * NN + pos] = i;
}

__global__ void k_deg(const int* __restrict__ dst) {
    int e = blockIdx.x * blockDim.x + threadIdx.x;
    if (e >= EE) return;
    atomicAdd(&g_deg[dst[e]], 1.0f);
}

__global__ void k_deginv() {
    int i = blockIdx.x * blockDim.x + threadIdx.x;
    if (i >= NN) return;
    g_deginv[i] = 1.0f / fmaxf(g_deg[i], 1.0f);
}

// ---------------- type-specific encoder (writes bf16 hi/lo directly) ----------------
#define ENC_SMEM ((2560 + 2688 + 16384 + 16384) * 4)

__global__ void __launch_bounds__(256, 1)
k_encoder(const int* __restrict__ z, const float* __restrict__ sd,
          const float* __restrict__ dfp, const float* __restrict__ cond,
          const float* __restrict__ mult, const float* __restrict__ zemb,
          const float* __restrict__ W1, const float* __restrict__ b1,
          const float* __restrict__ W2, const float* __restrict__ b2) {
    int t = blockIdx.y;
    int cnt = g_tcount[t];
    int start = blockIdx.x * 128;
    if (start >= cnt) return;

    extern __shared__ float sm[];
    float* W1s  = sm;
    float* raws = W1s + 2560;
    float* h1s  = raws + 2688;
    float* W2s  = h1s + 16384;
    __shared__ int nl[128];

    int tid = threadIdx.x;
    if (tid < 128) {
        int idx = start + tid;
        nl[tid] = g_tlist[(size_t)t * NN + (idx < cnt ? idx : cnt - 1)];
    }
    for (int i = tid; i < 640; i += 256)
        *(float4*)&W1s[i * 4] = *(const float4*)&W1[(size_t)t * 2560 + i * 4];
    for (int i = tid; i < 4096; i += 256)
        *(float4*)&W2s[i * 4] = *(const float4*)&W2[(size_t)t * 16384 + i * 4];
    __syncthreads();

    for (int i = tid; i < 128 * INDIM; i += 256) {
        int n = i / INDIM, k = i % INDIM;
        int node = nl[n];
        float v;
        if (k < 16)       v = zemb[(size_t)z[node] * 16 + k];
        else if (k == 16) v = sd[node];
        else if (k == 17) v = dfp[node];
        else if (k == 18) v = cond[node];
        else              v = mult[node];
        raws[n * 21 + k] = v;
    }
    __syncthreads();

    {
        int n = tid & 127;
        float r20[INDIM];
#pragma unroll
        for (int k = 0; k < INDIM; k++) r20[k] = raws[n * 21 + k];
        int chalf = tid >> 7;
        for (int p = 0; p < 64; p++) {
            int c = chalf + p * 2;
            float s = b1[t * HID + c];
#pragma unroll
            for (int k = 0; k < INDIM; k++) s += r20[k] * W1s[k * 128 + c];
            h1s[c * 128 + n] = fmaxf(s, 0.f);
        }
    }
    __syncthreads();

    int tx = tid & 15, ty = tid >> 4;
    float acc[8][8] = {};
    for (int k = 0; k < 128; k++) {
        float4 a0 = *(const float4*)&h1s[k * 128 + ty * 8];
        float4 a1 = *(const float4*)&h1s[k * 128 + ty * 8 + 4];
        float4 w0 = *(const float4*)&W2s[k * 128 + tx * 8];
        float4 w1 = *(const float4*)&W2s[k * 128 + tx * 8 + 4];
        float av[8] = {a0.x, a0.y, a0.z, a0.w, a1.x, a1.y, a1.z, a1.w};
        float wv[8] = {w0.x, w0.y, w0.z, w0.w, w1.x, w1.y, w1.z, w1.w};
#pragma unroll
        for (int i = 0; i < 8; i++)
#pragma unroll
            for (int j = 0; j < 8; j++) acc[i][j] += av[i] * wv[j];
    }
    int c0 = tx * 8;
    float bb[8];
#pragma unroll
    for (int j = 0; j < 8; j++) bb[j] = b2[t * HID + c0 + j];
    for (int i = 0; i < 8; i++) {
        int gi = start + ty * 8 + i;
        if (gi >= cnt) break;
        int node = nl[ty * 8 + i];
        __nv_bfloat162 hi[4], lo[4];
#pragma unroll
        for (int q = 0; q < 4; q++)
            split2(acc[i][2 * q] + bb[2 * q], acc[i][2 * q + 1] + bb[2 * q + 1], &hi[q], &lo[q]);
        *(float4*)&g_xh[(size_t)node * HID + c0] = *(float4*)hi;
        *(float4*)&g_xl[(size_t)node * HID + c0] = *(float4*)lo;
    }
}

// ---------------- weight prep: B[n][k] = W[k][n], hi/lo bf16 split ----------------
__global__ void k_prepB(const float* __restrict__ relW, const float* __restrict__ linW) {
    int i = blockIdx.x * blockDim.x + threadIdx.x;
    if (i >= 2 * 512 * 128) return;
    int l = i >> 16;
    int rem = i & 65535;
    int n = rem >> 7, k = rem & 127;
    int jt = n >> 7, c = n & 127;
    float v = (jt < 3) ? relW[(((size_t)l * 3 + jt) * 128 + k) * 128 + c]
                       : linW[((size_t)l * 128 + k) * 128 + c];
    __nv_bfloat16 hi = __float2bfloat16(v);
    __nv_bfloat16 lo = __float2bfloat16(v - __bfloat162float(hi));
    g_Bh[i] = hi;
    g_Bl[i] = lo;
}

// ---------------- bf16 mma.sync GEMM: [128 rows] x [128 k] x [128 cols/block] ----------------
// grid (NPAD/128, 4): blockIdx.y picks col chunk (rel 0..2 | lin)
// smem: 4 tiles [128][KS] bf16, KS=136 padded stride (bank-conflict-free frags)
#define KS 136
#define TILE_B (128 * KS * 2)
#define MMA_SMEM (4 * TILE_B)

__global__ void __launch_bounds__(256, 1)
k_mma(int l, const float* __restrict__ linb) {
    extern __shared__ __nv_bfloat16 smb[];
    __nv_bfloat16* Ah = smb;
    __nv_bfloat16* Al = Ah + 128 * KS;
    __nv_bfloat16* Bh = Al + 128 * KS;
    __nv_bfloat16* Bl = Bh + 128 * KS;

    int tid = threadIdx.x;
    int wid = tid >> 5, lane = tid & 31;
    int jt = blockIdx.y;
    int rowBase = blockIdx.x * 128;

    // global -> smem (8 bf16 per thread-iter)
    const __nv_bfloat16* gBh = g_Bh + ((size_t)l * 512 + jt * 128) * 128;
    const __nv_bfloat16* gBl = g_Bl + ((size_t)l * 512 + jt * 128) * 128;
    for (int i = tid; i < 2048; i += 256) {
        int row = i >> 4, kc = (i & 15) * 8;
        size_t go = (size_t)(rowBase + row) * 128 + kc;
        int so = row * KS + kc;
        *(float4*)&Ah[so] = *(const float4*)&g_xh[go];
        *(float4*)&Al[so] = *(const float4*)&g_xl[go];
        *(float4*)&Bh[so] = *(const float4*)&gBh[(size_t)row * 128 + kc];
        *(float4*)&Bl[so] = *(const float4*)&gBl[(size_t)row * 128 + kc];
    }
    __syncthreads();

    // warp tiling: 4 (m) x 2 (n); warp tile 32m x 64n
    int wm = wid >> 1, wn = wid & 1;
    int g = lane >> 2, tc = lane & 3;

    float c[2][8][4];
#pragma unroll
    for (int mt = 0; mt < 2; mt++)
#pragma unroll
        for (int nt = 0; nt < 8; nt++)
#pragma unroll
            for (int q = 0; q < 4; q++) c[mt][nt][q] = 0.f;

    const __nv_bfloat16* Asel[3] = {Ah, Ah, Al};
    const __nv_bfloat16* Bsel[3] = {Bh, Bl, Bh};

#pragma unroll
    for (int p = 0; p < 3; p++) {
        const __nv_bfloat16* A = Asel[p];
        const __nv_bfloat16* B = Bsel[p];
#pragma unroll
        for (int k0 = 0; k0 < 8; k0++) {
            int kb = k0 * 16 + tc * 2;
            uint32_t a[2][4];
#pragma unroll
            for (int mt = 0; mt < 2; mt++) {
                int r0 = wm * 32 + mt * 16 + g;
                a[mt][0] = *(const uint32_t*)&A[r0 * KS + kb];
                a[mt][1] = *(const uint32_t*)&A[(r0 + 8) * KS + kb];
                a[mt][2] = *(const uint32_t*)&A[r0 * KS + kb + 8];
                a[mt][3] = *(const uint32_t*)&A[(r0 + 8) * KS + kb + 8];
            }
            uint32_t b[8][2];
#pragma unroll
            for (int nt = 0; nt < 8; nt++) {
                int col = wn * 64 + nt * 8 + g;
                b[nt][0] = *(const uint32_t*)&B[col * KS + kb];
                b[nt][1] = *(const uint32_t*)&B[col * KS + kb + 8];
            }
#pragma unroll
            for (int mt = 0; mt < 2; mt++)
#pragma unroll
                for (int nt = 0; nt < 8; nt++) {
                    float* cc = c[mt][nt];
                    asm volatile(
                        "mma.sync.aligned.m16n8k16.row.col.f32.bf16.bf16.f32 "
                        "{%0,%1,%2,%3}, {%4,%5,%6,%7}, {%8,%9}, {%0,%1,%2,%3};"
                        : "+f"(cc[0]), "+f"(cc[1]), "+f"(cc[2]), "+f"(cc[3])
                        : "r"(a[mt][0]), "r"(a[mt][1]), "r"(a[mt][2]), "r"(a[mt][3]),
                          "r"(b[nt][0]), "r"(b[nt][1]));
                }
        }
    }

    // epilogue
#pragma unroll
    for (int mt = 0; mt < 2; mt++) {
        int row0 = rowBase + wm * 32 + mt * 16 + g;
        int row1 = row0 + 8;
#pragma unroll
        for (int nt = 0; nt < 8; nt++) {
            int colLoc = wn * 64 + nt * 8 + tc * 2;
            float* cc = c[mt][nt];
            if (jt < 3) {
                size_t o0 = (size_t)row0 * 384 + jt * 128 + colLoc;
                size_t o1 = (size_t)row1 * 384 + jt * 128 + colLoc;
                if (row0 < NN) *(float2*)&g_y[o0] = make_float2(cc[0], cc[1]);
                if (row1 < NN) *(float2*)&g_y[o1] = make_float2(cc[2], cc[3]);
            } else {
                float b0 = linb[colLoc], b1 = linb[colLoc + 1];
                if (row0 < NN)
                    *(float2*)&g_h[(size_t)row0 * 128 + colLoc] = make_float2(cc[0] + b0, cc[1] + b1);
                if (row1 < NN)
                    *(float2*)&g_h[(size_t)row1 * 128 + colLoc] = make_float2(cc[2] + b0, cc[3] + b1);
            }
        }
    }
}

// ---------------- sparse scatter: h[dst] += y[src, et] * deginv[dst] ----------------
__global__ void k_edge(const int* __restrict__ src, const int* __restrict__ dst,
                       const int* __restrict__ etyp) {
    int w = (blockIdx.x * blockDim.x + threadIdx.x) >> 5;
    if (w >= EE) return;
    int lane = threadIdx.x & 31;
    int s = src[w];
    int d = dst[w];
    int r = etyp[w];
    float sc = g_deginv[d];
    float4 v = *(const float4*)&g_y[(size_t)s * (NREL * HID) + r * HID + lane * 4];
    float4 o = make_float4(v.x * sc, v.y * sc, v.z * sc, v.w * sc);
    float* p = &g_h[(size_t)d * HID + lane * 4];
    asm volatile("red.global.add.v4.f32 [%0], {%1,%2,%3,%4};"
                 :: "l"(p), "f"(o.x), "f"(o.y), "f"(o.z), "f"(o.w)
                 : "memory");
}

// ---------------- LayerNorm (writes fp32 x AND bf16 hi/lo) ----------------
__global__ void k_ln(const float* __restrict__ g, const float* __restrict__ b) {
    int warp = threadIdx.x >> 5, lane = threadIdx.x & 31;
    int node = blockIdx.x * 8 + warp;
    if (node >= NN) return;
    float4 v = *(const float4*)&g_h[(size_t)node * HID + lane * 4];
    float s = v.x + v.y + v.z + v.w;
#pragma unroll
    for (int o = 16; o; o >>= 1) s += __shfl_xor_sync(0xFFFFFFFFu, s, o);
    float mu = s * (1.0f / HID);
    float dx = v.x - mu, dy = v.y - mu, dz = v.z - mu, dw = v.w - mu;
    float s2 = dx * dx + dy * dy + dz * dz + dw * dw;
#pragma unroll
    for (int o = 16; o; o >>= 1) s2 += __shfl_xor_sync(0xFFFFFFFFu, s2, o);
    float rs = rsqrtf(s2 * (1.0f / HID) + LN_EPS);
    int c = lane * 4;
    float4 gg = *(const float4*)&g[c];
    float4 bb = *(const float4*)&b[c];
    float4 o = make_float4(dx * rs * gg.x + bb.x, dy * rs * gg.y + bb.y,
                           dz * rs * gg.z + bb.z, dw * rs * gg.w + bb.w);
    *(float4*)&g_x[(size_t)node * HID + c] = o;
    __nv_bfloat162 hi0, lo0, hi1, lo1;
    split2(o.x, o.y, &hi0, &lo0);
    split2(o.z, o.w, &hi1, &lo1);
    *(float2*)&g_xh[(size_t)node * HID + c] = make_float2(__uint_as_float(*(uint32_t*)&hi0),
                                                          __uint_as_float(*(uint32_t*)&hi1));
    *(float2*)&g_xl[(size_t)node * HID + c] = make_float2(__uint_as_float(*(uint32_t*)&lo0),
                                                          __uint_as_float(*(uint32_t*)&lo1));
}

// ---------------- pooling + regressor ----------------
__global__ void k_pool() {
    int c = threadIdx.x;
    int base = blockIdx.x * 256;
    float s = 0.f;
    for (int n = 0; n < 256; n++) {
        int node = base + n;
        if (node >= NN) break;
        s += g_x[(size_t)node * HID + c];
    }
    atomicAdd(&g_pool[c], s);
}

__global__ void k_final(const float* __restrict__ regW, const float* __restrict__ regb,
                        float* __restrict__ out) {
    int c = threadIdx.x;
    __shared__ float red[HID];
    red[c] = g_pool[c] * (1.0f / NN) * regW[c];
    __syncthreads();
    for (int s = 64; s; s >>= 1) {
        if (c < s) red[c] += red[c + s];
        __syncthreads();
    }
    if (c == 0) out[0] = red[0] + regb[0];
}

// ---------------- launch ----------------
extern "C" void kernel_launch(void* const* d_in, const int* in_sizes, int n_in,
                              void* d_out, int out_size) {
    const int*   z     = (const int*)d_in[0];
    const float* sd    = (const float*)d_in[1];
    const float* dfp   = (const float*)d_in[2];
    const float* cond  = (const float*)d_in[3];
    const float* mult  = (const float*)d_in[4];
    const int*   ntype = (const int*)d_in[5];
    const int*   eidx  = (const int*)d_in[6];
    const int*   etyp  = (const int*)d_in[7];
    const float* zemb  = (const float*)d_in[8];
    const float* eW1   = (const float*)d_in[9];
    const float* eb1   = (const float*)d_in[10];
    const float* eW2   = (const float*)d_in[11];
    const float* eb2   = (const float*)d_in[12];
    const float* linW  = (const float*)d_in[13];
    const float* linb  = (const float*)d_in[14];
    const float* relW  = (const float*)d_in[15];
    const float* lng   = (const float*)d_in[16];
    const float* lnb   = (const float*)d_in[17];
    const float* regW  = (const float*)d_in[18];
    const float* regb  = (const float*)d_in[19];
    float* out = (float*)d_out;

    cudaFuncSetAttribute(k_encoder, cudaFuncAttributeMaxDynamicSharedMemorySize, ENC_SMEM);
    cudaFuncSetAttribute(k_mma, cudaFuncAttributeMaxDynamicSharedMemorySize, MMA_SMEM);

    const int rowBlocks = NPAD / 128;   // 782

    k_init<<<(NN + 255) / 256, 256>>>();
    k_bucket<<<(NN + 255) / 256, 256>>>(ntype);
    k_deg<<<(EE + 255) / 256, 256>>>(eidx + EE);
    k_deginv<<<(NN + 255) / 256, 256>>>();
    k_encoder<<<dim3(rowBlocks, NTYPE), 256, ENC_SMEM>>>(z, sd, dfp, cond, mult,
                                                         zemb, eW1, eb1, eW2, eb2);
    k_prepB<<<512, 256>>>(relW, linW);
    for (int l = 0; l < 2; l++) {
        k_mma<<<dim3(rowBlocks, 4), 256, MMA_SMEM>>>(l, linb + l * HID);
        k_edge<<<EE / 8, 256>>>(eidx, eidx + EE, etyp);
        k_ln<<<NN / 8, 256>>>(lng + l * HID, lnb + l * HID);
    }
    k_pool<<<(NN + 255) / 256, 128>>>();
    k_final<<<1, 128>>>(regW, regb, out);
}

// round 4
// speedup vs baseline: 2.0493x; 1.5327x over previous
#include <cuda_runtime.h>
#include <cuda_bf16.h>
#include <cuda_fp16.h>
#include <cstdint>

#define NN    100000
#define NPAD  100096
#define EE    1600000
#define HID   128
#define INDIM 20
#define NREL  3
#define NTYPE 4
#define LN_EPS 1e-5f

// ---------------- device scratch (no allocs allowed) ----------------
static __device__ float g_x[(size_t)NN * HID];             // node features fp32 (pool input)
static __device__ float g_h[(size_t)NN * HID];             // x@lin + b (pre-agg)
static __device__ __half g_yh[(size_t)NN * NREL * HID];    // per-relation feats fp16 (76.8MB, L2-fits)
static __device__ __nv_bfloat16 g_xh[(size_t)NPAD * HID];  // x hi (bf16); pad rows stay 0
static __device__ __nv_bfloat16 g_xl[(size_t)NPAD * HID];  // x lo residual
static __device__ __nv_bfloat16 g_Bh[2 * 512 * 128];       // weights B[n][k] hi, per layer
static __device__ __nv_bfloat16 g_Bl[2 * 512 * 128];       // weights lo
static __device__ int   g_cnt[NN];                         // in-degree
static __device__ int   g_roff[NN];                        // CSR row offsets (exclusive scan)
static __device__ int   g_cur[NN];                         // fill cursors
static __device__ int   g_csr[EE];                         // packed (src<<2)|etype, grouped by dst
static __device__ int   g_bsum[512];                       // block partial sums for scan
static __device__ int   g_tlist[(size_t)NTYPE * NN];
static __device__ int   g_tcount[NTYPE];
static __device__ float g_pool[HID];

// ---------------- split helper ----------------
__device__ __forceinline__ void split2(float a, float b, __nv_bfloat162* hi, __nv_bfloat162* lo) {
    __nv_bfloat16 ha = __float2bfloat16(a), hb = __float2bfloat16(b);
    *hi = __nv_bfloat162(ha, hb);
    *lo = __nv_bfloat162(__float2bfloat16(a - __bfloat162float(ha)),
                         __float2bfloat16(b - __bfloat162float(hb)));
}

// ---------------- init / bucketing / CSR build ----------------
__global__ void k_init() {
    int i = blockIdx.x * blockDim.x + threadIdx.x;
    if (i < NN) { g_cnt[i] = 0; g_cur[i] = 0; }
    if (i < NTYPE) g_tcount[i] = 0;
    if (i < HID) g_pool[i] = 0.f;
    if (i < 512) g_bsum[i] = 0;
}

__global__ void k_bucket(const int* __restrict__ ntype) {
    int i = blockIdx.x * blockDim.x + threadIdx.x;
    if (i >= NN) return;
    int t = ntype[i];
    int pos = atomicAdd(&g_tcount[t], 1);
    g_tlist[(size_t)t * NN + pos] = i;
}

__global__ void k_cnt(const int* __restrict__ dst) {
    int e = blockIdx.x * blockDim.x + threadIdx.x;
    if (e >= EE) return;
    atomicAdd(&g_cnt[dst[e]], 1);
}

// block-level exclusive scan of g_cnt -> g_roff, block totals -> g_bsum
__global__ void k_scan1() {
    __shared__ int sh[256];
    int i = blockIdx.x * 256 + threadIdx.x;
    int v = (i < NN) ? g_cnt[i] : 0;
    sh[threadIdx.x] = v;
    __syncthreads();
    for (int o = 1; o < 256; o <<= 1) {
        int t = (threadIdx.x >= o) ? sh[threadIdx.x - o] : 0;
        __syncthreads();
        sh[threadIdx.x] += t;
        __syncthreads();
    }
    if (i < NN) g_roff[i] = sh[threadIdx.x] - v;
    if (threadIdx.x == 255) g_bsum[blockIdx.x] = sh[255];
}

__global__ void k_scan2() {   // 1 block, 512 threads over 391 block sums
    __shared__ int sh[512];
    int t = threadIdx.x;
    int v = g_bsum[t];
    sh[t] = v;
    __syncthreads();
    for (int o = 1; o < 512; o <<= 1) {
        int u = (t >= o) ? sh[t - o] : 0;
        __syncthreads();
        sh[t] += u;
        __syncthreads();
    }
    g_bsum[t] = sh[t] - v;   // exclusive
}

__global__ void k_scan3() {
    int i = blockIdx.x * blockDim.x + threadIdx.x;
    if (i >= NN) return;
    g_roff[i] += g_bsum[i >> 8];
}

__global__ void k_fill(const int* __restrict__ src, const int* __restrict__ dst,
                       const int* __restrict__ etyp) {
    int e = blockIdx.x * blockDim.x + threadIdx.x;
    if (e >= EE) return;
    int d = dst[e];
    int pos = g_roff[d] + atomicAdd(&g_cur[d], 1);
    g_csr[pos] = (src[e] << 2) | etyp[e];
}

// ---------------- type-specific encoder (writes bf16 hi/lo directly) ----------------
#define ENC_SMEM ((2560 + 2688 + 16384 + 16384) * 4)

__global__ void __launch_bounds__(256, 1)
k_encoder(const int* __restrict__ z, const float* __restrict__ sd,
          const float* __restrict__ dfp, const float* __restrict__ cond,
          const float* __restrict__ mult, const float* __restrict__ zemb,
          const float* __restrict__ W1, const float* __restrict__ b1,
          const float* __restrict__ W2, const float* __restrict__ b2) {
    int t = blockIdx.y;
    int cnt = g_tcount[t];
    int start = blockIdx.x * 128;
    if (start >= cnt) return;

    extern __shared__ float sm[];
    float* W1s  = sm;
    float* raws = W1s + 2560;
    float* h1s  = raws + 2688;
    float* W2s  = h1s + 16384;
    __shared__ int nl[128];

    int tid = threadIdx.x;
    if (tid < 128) {
        int idx = start + tid;
        nl[tid] = g_tlist[(size_t)t * NN + (idx < cnt ? idx : cnt - 1)];
    }
    for (int i = tid; i < 640; i += 256)
        *(float4*)&W1s[i * 4] = *(const float4*)&W1[(size_t)t * 2560 + i * 4];
    for (int i = tid; i < 4096; i += 256)
        *(float4*)&W2s[i * 4] = *(const float4*)&W2[(size_t)t * 16384 + i * 4];
    __syncthreads();

    for (int i = tid; i < 128 * INDIM; i += 256) {
        int n = i / INDIM, k = i % INDIM;
        int node = nl[n];
        float v;
        if (k < 16)       v = zemb[(size_t)z[node] * 16 + k];
        else if (k == 16) v = sd[node];
        else if (k == 17) v = dfp[node];
        else if (k == 18) v = cond[node];
        else              v = mult[node];
        raws[n * 21 + k] = v;
    }
    __syncthreads();

    {
        int n = tid & 127;
        float r20[INDIM];
#pragma unroll
        for (int k = 0; k < INDIM; k++) r20[k] = raws[n * 21 + k];
        int chalf = tid >> 7;
        for (int p = 0; p < 64; p++) {
            int c = chalf + p * 2;
            float s = b1[t * HID + c];
#pragma unroll
            for (int k = 0; k < INDIM; k++) s += r20[k] * W1s[k * 128 + c];
            h1s[c * 128 + n] = fmaxf(s, 0.f);
        }
    }
    __syncthreads();

    int tx = tid & 15, ty = tid >> 4;
    float acc[8][8] = {};
    for (int k = 0; k < 128; k++) {
        float4 a0 = *(const float4*)&h1s[k * 128 + ty * 8];
        float4 a1 = *(const float4*)&h1s[k * 128 + ty * 8 + 4];
        float4 w0 = *(const float4*)&W2s[k * 128 + tx * 8];
        float4 w1 = *(const float4*)&W2s[k * 128 + tx * 8 + 4];
        float av[8] = {a0.x, a0.y, a0.z, a0.w, a1.x, a1.y, a1.z, a1.w};
        float wv[8] = {w0.x, w0.y, w0.z, w0.w, w1.x, w1.y, w1.z, w1.w};
#pragma unroll
        for (int i = 0; i < 8; i++)
#pragma unroll
            for (int j = 0; j < 8; j++) acc[i][j] += av[i] * wv[j];
    }
    int c0 = tx * 8;
    float bb[8];
#pragma unroll
    for (int j = 0; j < 8; j++) bb[j] = b2[t * HID + c0 + j];
    for (int i = 0; i < 8; i++) {
        int gi = start + ty * 8 + i;
        if (gi >= cnt) break;
        int node = nl[ty * 8 + i];
        __nv_bfloat162 hi[4], lo[4];
#pragma unroll
        for (int q = 0; q < 4; q++)
            split2(acc[i][2 * q] + bb[2 * q], acc[i][2 * q + 1] + bb[2 * q + 1], &hi[q], &lo[q]);
        *(float4*)&g_xh[(size_t)node * HID + c0] = *(float4*)hi;
        *(float4*)&g_xl[(size_t)node * HID + c0] = *(float4*)lo;
    }
}

// ---------------- weight prep: B[n][k] = W[k][n], hi/lo bf16 split ----------------
__global__ void k_prepB(const float* __restrict__ relW, const float* __restrict__ linW) {
    int i = blockIdx.x * blockDim.x + threadIdx.x;
    if (i >= 2 * 512 * 128) return;
    int l = i >> 16;
    int rem = i & 65535;
    int n = rem >> 7, k = rem & 127;
    int jt = n >> 7, c = n & 127;
    float v = (jt < 3) ? relW[(((size_t)l * 3 + jt) * 128 + k) * 128 + c]
                       : linW[((size_t)l * 128 + k) * 128 + c];
    __nv_bfloat16 hi = __float2bfloat16(v);
    __nv_bfloat16 lo = __float2bfloat16(v - __bfloat162float(hi));
    g_Bh[i] = hi;
    g_Bl[i] = lo;
}

// ---------------- bf16 mma.sync GEMM: [128 rows] x [128 k] x [128 cols/block] ----------------
#define KS 136
#define MMA_SMEM (4 * 128 * KS * 2)

__global__ void __launch_bounds__(256, 1)
k_mma(int l, const float* __restrict__ linb) {
    extern __shared__ __nv_bfloat16 smb[];
    __nv_bfloat16* Ah = smb;
    __nv_bfloat16* Al = Ah + 128 * KS;
    __nv_bfloat16* Bh = Al + 128 * KS;
    __nv_bfloat16* Bl = Bh + 128 * KS;

    int tid = threadIdx.x;
    int wid = tid >> 5, lane = tid & 31;
    int jt = blockIdx.y;
    int rowBase = blockIdx.x * 128;

    const __nv_bfloat16* gBh = g_Bh + ((size_t)l * 512 + jt * 128) * 128;
    const __nv_bfloat16* gBl = g_Bl + ((size_t)l * 512 + jt * 128) * 128;
    for (int i = tid; i < 2048; i += 256) {
        int row = i >> 4, kc = (i & 15) * 8;
        size_t go = (size_t)(rowBase + row) * 128 + kc;
        int so = row * KS + kc;
        *(float4*)&Ah[so] = *(const float4*)&g_xh[go];
        *(float4*)&Al[so] = *(const float4*)&g_xl[go];
        *(float4*)&Bh[so] = *(const float4*)&gBh[(size_t)row * 128 + kc];
        *(float4*)&Bl[so] = *(const float4*)&gBl[(size_t)row * 128 + kc];
    }
    __syncthreads();

    int wm = wid >> 1, wn = wid & 1;
    int g = lane >> 2, tc = lane & 3;

    float c[2][8][4];
#pragma unroll
    for (int mt = 0; mt < 2; mt++)
#pragma unroll
        for (int nt = 0; nt < 8; nt++)
#pragma unroll
            for (int q = 0; q < 4; q++) c[mt][nt][q] = 0.f;

    const __nv_bfloat16* Asel[3] = {Ah, Ah, Al};
    const __nv_bfloat16* Bsel[3] = {Bh, Bl, Bh};

#pragma unroll
    for (int p = 0; p < 3; p++) {
        const __nv_bfloat16* A = Asel[p];
        const __nv_bfloat16* B = Bsel[p];
#pragma unroll
        for (int k0 = 0; k0 < 8; k0++) {
            int kb = k0 * 16 + tc * 2;
            uint32_t a[2][4];
#pragma unroll
            for (int mt = 0; mt < 2; mt++) {
                int r0 = wm * 32 + mt * 16 + g;
                a[mt][0] = *(const uint32_t*)&A[r0 * KS + kb];
                a[mt][1] = *(const uint32_t*)&A[(r0 + 8) * KS + kb];
                a[mt][2] = *(const uint32_t*)&A[r0 * KS + kb + 8];
                a[mt][3] = *(const uint32_t*)&A[(r0 + 8) * KS + kb + 8];
            }
            uint32_t b[8][2];
#pragma unroll
            for (int nt = 0; nt < 8; nt++) {
                int col = wn * 64 + nt * 8 + g;
                b[nt][0] = *(const uint32_t*)&B[col * KS + kb];
                b[nt][1] = *(const uint32_t*)&B[col * KS + kb + 8];
            }
#pragma unroll
            for (int mt = 0; mt < 2; mt++)
#pragma unroll
                for (int nt = 0; nt < 8; nt++) {
                    float* cc = c[mt][nt];
                    asm volatile(
                        "mma.sync.aligned.m16n8k16.row.col.f32.bf16.bf16.f32 "
                        "{%0,%1,%2,%3}, {%4,%5,%6,%7}, {%8,%9}, {%0,%1,%2,%3};"
                        : "+f"(cc[0]), "+f"(cc[1]), "+f"(cc[2]), "+f"(cc[3])
                        : "r"(a[mt][0]), "r"(a[mt][1]), "r"(a[mt][2]), "r"(a[mt][3]),
                          "r"(b[nt][0]), "r"(b[nt][1]));
                }
        }
    }

    // epilogue: rel chunks -> fp16 y, lin chunk -> fp32 h (+bias)
#pragma unroll
    for (int mt = 0; mt < 2; mt++) {
        int row0 = rowBase + wm * 32 + mt * 16 + g;
        int row1 = row0 + 8;
#pragma unroll
        for (int nt = 0; nt < 8; nt++) {
            int colLoc = wn * 64 + nt * 8 + tc * 2;
            float* cc = c[mt][nt];
            if (jt < 3) {
                size_t o0 = (size_t)row0 * 384 + jt * 128 + colLoc;
                size_t o1 = (size_t)row1 * 384 + jt * 128 + colLoc;
                if (row0 < NN) *(__half2*)&g_yh[o0] = __floats2half2_rn(cc[0], cc[1]);
                if (row1 < NN) *(__half2*)&g_yh[o1] = __floats2half2_rn(cc[2], cc[3]);
            } else {
                float b0 = linb[colLoc], b1 = linb[colLoc + 1];
                if (row0 < NN)
                    *(float2*)&g_h[(size_t)row0 * 128 + colLoc] = make_float2(cc[0] + b0, cc[1] + b1);
                if (row1 < NN)
                    *(float2*)&g_h[(size_t)row1 * 128 + colLoc] = make_float2(cc[2] + b0, cc[3] + b1);
            }
        }
    }
}

// ---------------- fused CSR aggregation + LayerNorm ----------------
// one warp per dst node; 8 edges in flight; writes g_x + bf16 hi/lo
__global__ void __launch_bounds__(256)
k_aggr_ln(const float* __restrict__ gg, const float* __restrict__ gb) {
    int warp = threadIdx.x >> 5, lane = threadIdx.x & 31;
    int node = blockIdx.x * 8 + warp;
    if (node >= NN) return;
    int base = g_roff[node];
    int cnt  = g_cnt[node];

    float a0 = 0.f, a1 = 0.f, a2 = 0.f, a3 = 0.f;
    for (int j0 = 0; j0 < cnt; j0 += 8) {
        int v[8];
        uint2 u[8];
#pragma unroll
        for (int q = 0; q < 8; q++)
            v[q] = (j0 + q < cnt) ? __ldg(&g_csr[base + j0 + q]) : -1;
#pragma unroll
        for (int q = 0; q < 8; q++) {
            if (v[q] >= 0) {
                int s = v[q] >> 2, r = v[q] & 3;
                u[q] = *(const uint2*)&g_yh[((size_t)s * NREL + r) * HID + lane * 4];
            } else {
                u[q] = make_uint2(0u, 0u);
            }
        }
#pragma unroll
        for (int q = 0; q < 8; q++) {
            float2 f0 = __half22float2(*(__half2*)&u[q].x);
            float2 f1 = __half22float2(*(__half2*)&u[q].y);
            a0 += f0.x; a1 += f0.y; a2 += f1.x; a3 += f1.y;
        }
    }
    float di = 1.0f / fmaxf((float)cnt, 1.0f);

    int c = lane * 4;
    float4 hv = *(const float4*)&g_h[(size_t)node * HID + c];
    hv.x += a0 * di; hv.y += a1 * di; hv.z += a2 * di; hv.w += a3 * di;

    float s = hv.x + hv.y + hv.z + hv.w;
#pragma unroll
    for (int o = 16; o; o >>= 1) s += __shfl_xor_sync(0xFFFFFFFFu, s, o);
    float mu = s * (1.0f / HID);
    float dx = hv.x - mu, dy = hv.y - mu, dz = hv.z - mu, dw = hv.w - mu;
    float s2 = dx * dx + dy * dy + dz * dz + dw * dw;
#pragma unroll
    for (int o = 16; o; o >>= 1) s2 += __shfl_xor_sync(0xFFFFFFFFu, s2, o);
    float rs = rsqrtf(s2 * (1.0f / HID) + LN_EPS);

    float4 g4 = *(const float4*)&gg[c];
    float4 b4 = *(const float4*)&gb[c];
    float4 o = make_float4(dx * rs * g4.x + b4.x, dy * rs * g4.y + b4.y,
                           dz * rs * g4.z + b4.z, dw * rs * g4.w + b4.w);
    *(float4*)&g_x[(size_t)node * HID + c] = o;

    __nv_bfloat162 hi0, lo0, hi1, lo1;
    split2(o.x, o.y, &hi0, &lo0);
    split2(o.z, o.w, &hi1, &lo1);
    *(float2*)&g_xh[(size_t)node * HID + c] = make_float2(__uint_as_float(*(uint32_t*)&hi0),
                                                          __uint_as_float(*(uint32_t*)&hi1));
    *(float2*)&g_xl[(size_t)node * HID + c] = make_float2(__uint_as_float(*(uint32_t*)&lo0),
                                                          __uint_as_float(*(uint32_t*)&lo1));
}

// ---------------- pooling + regressor ----------------
__global__ void k_pool() {
    int c = threadIdx.x;
    int base = blockIdx.x * 256;
    float s = 0.f;
    for (int n = 0; n < 256; n++) {
        int node = base + n;
        if (node >= NN) break;
        s += g_x[(size_t)node * HID + c];
    }
    atomicAdd(&g_pool[c], s);
}

__global__ void k_final(const float* __restrict__ regW, const float* __restrict__ regb,
                        float* __restrict__ out) {
    int c = threadIdx.x;
    __shared__ float red[HID];
    red[c] = g_pool[c] * (1.0f / NN) * regW[c];
    __syncthreads();
    for (int s = 64; s; s >>= 1) {
        if (c < s) red[c] += red[c + s];
        __syncthreads();
    }
    if (c == 0) out[0] = red[0] + regb[0];
}

// ---------------- launch ----------------
extern "C" void kernel_launch(void* const* d_in, const int* in_sizes, int n_in,
                              void* d_out, int out_size) {
    const int*   z     = (const int*)d_in[0];
    const float* sd    = (const float*)d_in[1];
    const float* dfp   = (const float*)d_in[2];
    const float* cond  = (const float*)d_in[3];
    const float* mult  = (const float*)d_in[4];
    const int*   ntype = (const int*)d_in[5];
    const int*   eidx  = (const int*)d_in[6];
    const int*   etyp  = (const int*)d_in[7];
    const float* zemb  = (const float*)d_in[8];
    const float* eW1   = (const float*)d_in[9];
    const float* eb1   = (const float*)d_in[10];
    const float* eW2   = (const float*)d_in[11];
    const float* eb2   = (const float*)d_in[12];
    const float* linW  = (const float*)d_in[13];
    const float* linb  = (const float*)d_in[14];
    const float* relW  = (const float*)d_in[15];
    const float* lng   = (const float*)d_in[16];
    const float* lnb   = (const float*)d_in[17];
    const float* regW  = (const float*)d_in[18];
    const float* regb  = (const float*)d_in[19];
    float* out = (float*)d_out;

    cudaFuncSetAttribute(k_encoder, cudaFuncAttributeMaxDynamicSharedMemorySize, ENC_SMEM);
    cudaFuncSetAttribute(k_mma, cudaFuncAttributeMaxDynamicSharedMemorySize, MMA_SMEM);

    const int rowBlocks = NPAD / 128;   // 782

    k_init<<<(NN + 255) / 256, 256>>>();
    k_bucket<<<(NN + 255) / 256, 256>>>(ntype);
    k_cnt<<<(EE + 255) / 256, 256>>>(eidx + EE);
    k_scan1<<<(NN + 255) / 256, 256>>>();
    k_scan2<<<1, 512>>>();
    k_scan3<<<(NN + 255) / 256, 256>>>();
    k_fill<<<(EE + 255) / 256, 256>>>(eidx, eidx + EE, etyp);
    k_encoder<<<dim3(rowBlocks, NTYPE), 256, ENC_SMEM>>>(z, sd, dfp, cond, mult,
                                                         zemb, eW1, eb1, eW2, eb2);
    k_prepB<<<512, 256>>>(relW, linW);
    for (int l = 0; l < 2; l++) {
        k_mma<<<dim3(rowBlocks, 4), 256, MMA_SMEM>>>(l, linb + l * HID);
        k_aggr_ln<<<(NN + 7) / 8, 256>>>(lng + l * HID, lnb + l * HID);
    }
    k_pool<<<(NN + 255) / 256, 128>>>();
    k_final<<<1, 128>>>(regW, regb, out);
}

// round 5
// speedup vs baseline: 2.5361x; 1.2375x over previous
#include <cuda_runtime.h>
#include <cuda_fp16.h>
#include <cstdint>

#define NN    100000
#define NPAD  100096
#define EE    1600000
#define HID   128
#define INDIM 20
#define NREL  3
#define NTYPE 4
#define LN_EPS 1e-5f

// ---------------- device scratch (no allocs allowed) ----------------
static __device__ float  g_h[(size_t)NN * HID];            // x@lin + b (pre-agg)
static __device__ __half g_yh[(size_t)NN * NREL * HID];    // per-relation feats fp16 (76.8MB)
static __device__ __half g_xh[(size_t)NPAD * HID];         // x hi (fp16); pad rows stay 0
static __device__ __half g_xl[(size_t)NPAD * HID];         // x lo residual (fp16)
static __device__ __half g_Bw[2 * 512 * 128];              // weights B[n][k] fp16, per layer
static __device__ int    g_cnt[NN];
static __device__ int    g_roff[NN];
static __device__ int    g_cur[NN];
static __device__ int    g_csr[EE];                        // (src<<2)|etype, grouped by dst
static __device__ int    g_bsum[512];
static __device__ int    g_tlist[(size_t)NTYPE * NN];
static __device__ int    g_tcount[NTYPE];
static __device__ float  g_pool[HID];

// ---------------- fp16 hi/lo split helper ----------------
__device__ __forceinline__ void split2h(float a, float b, __half2* hi, __half2* lo) {
    __half ha = __float2half_rn(a), hb = __float2half_rn(b);
    *hi = __halves2half2(ha, hb);
    *lo = __halves2half2(__float2half_rn(a - __half2float(ha)),
                         __float2half_rn(b - __half2float(hb)));
}

// ---------------- init / bucketing / CSR build ----------------
__global__ void k_init() {
    int i = blockIdx.x * blockDim.x + threadIdx.x;
    if (i < NN) { g_cnt[i] = 0; g_cur[i] = 0; }
    if (i < NTYPE) g_tcount[i] = 0;
    if (i < HID) g_pool[i] = 0.f;
    if (i < 512) g_bsum[i] = 0;
}

__global__ void k_bucket(const int* __restrict__ ntype) {
    int i = blockIdx.x * blockDim.x + threadIdx.x;
    if (i >= NN) return;
    int t = ntype[i];
    int pos = atomicAdd(&g_tcount[t], 1);
    g_tlist[(size_t)t * NN + pos] = i;
}

__global__ void k_cnt(const int* __restrict__ dst) {
    int e = blockIdx.x * blockDim.x + threadIdx.x;
    if (e >= EE) return;
    atomicAdd(&g_cnt[dst[e]], 1);
}

__global__ void k_scan1() {
    __shared__ int sh[256];
    int i = blockIdx.x * 256 + threadIdx.x;
    int v = (i < NN) ? g_cnt[i] : 0;
    sh[threadIdx.x] = v;
    __syncthreads();
    for (int o = 1; o < 256; o <<= 1) {
        int t = (threadIdx.x >= o) ? sh[threadIdx.x - o] : 0;
        __syncthreads();
        sh[threadIdx.x] += t;
        __syncthreads();
    }
    if (i < NN) g_roff[i] = sh[threadIdx.x] - v;
    if (threadIdx.x == 255) g_bsum[blockIdx.x] = sh[255];
}

__global__ void k_scan2() {
    __shared__ int sh[512];
    int t = threadIdx.x;
    int v = g_bsum[t];
    sh[t] = v;
    __syncthreads();
    for (int o = 1; o < 512; o <<= 1) {
        int u = (t >= o) ? sh[t - o] : 0;
        __syncthreads();
        sh[t] += u;
        __syncthreads();
    }
    g_bsum[t] = sh[t] - v;
}

__global__ void k_scan3() {
    int i = blockIdx.x * blockDim.x + threadIdx.x;
    if (i >= NN) return;
    g_roff[i] += g_bsum[i >> 8];
}

__global__ void k_fill(const int* __restrict__ src, const int* __restrict__ dst,
                       const int* __restrict__ etyp) {
    int e = blockIdx.x * blockDim.x + threadIdx.x;
    if (e >= EE) return;
    int d = dst[e];
    int pos = g_roff[d] + atomicAdd(&g_cur[d], 1);
    g_csr[pos] = (src[e] << 2) | etyp[e];
}

// ---------------- type-specific encoder (writes fp16 hi/lo directly) ----------------
#define ENC_SMEM ((2560 + 2688 + 16384 + 16384) * 4)

__global__ void __launch_bounds__(256, 1)
k_encoder(const int* __restrict__ z, const float* __restrict__ sd,
          const float* __restrict__ dfp, const float* __restrict__ cond,
          const float* __restrict__ mult, const float* __restrict__ zemb,
          const float* __restrict__ W1, const float* __restrict__ b1,
          const float* __restrict__ W2, const float* __restrict__ b2) {
    int t = blockIdx.y;
    int cnt = g_tcount[t];
    int start = blockIdx.x * 128;
    if (start >= cnt) return;

    extern __shared__ float sm[];
    float* W1s  = sm;
    float* raws = W1s + 2560;
    float* h1s  = raws + 2688;
    float* W2s  = h1s + 16384;
    __shared__ int nl[128];

    int tid = threadIdx.x;
    if (tid < 128) {
        int idx = start + tid;
        nl[tid] = g_tlist[(size_t)t * NN + (idx < cnt ? idx : cnt - 1)];
    }
    for (int i = tid; i < 640; i += 256)
        *(float4*)&W1s[i * 4] = *(const float4*)&W1[(size_t)t * 2560 + i * 4];
    for (int i = tid; i < 4096; i += 256)
        *(float4*)&W2s[i * 4] = *(const float4*)&W2[(size_t)t * 16384 + i * 4];
    __syncthreads();

    for (int i = tid; i < 128 * INDIM; i += 256) {
        int n = i / INDIM, k = i % INDIM;
        int node = nl[n];
        float v;
        if (k < 16)       v = zemb[(size_t)z[node] * 16 + k];
        else if (k == 16) v = sd[node];
        else if (k == 17) v = dfp[node];
        else if (k == 18) v = cond[node];
        else              v = mult[node];
        raws[n * 21 + k] = v;
    }
    __syncthreads();

    {
        int n = tid & 127;
        float r20[INDIM];
#pragma unroll
        for (int k = 0; k < INDIM; k++) r20[k] = raws[n * 21 + k];
        int chalf = tid >> 7;
        for (int p = 0; p < 64; p++) {
            int c = chalf + p * 2;
            float s = b1[t * HID + c];
#pragma unroll
            for (int k = 0; k < INDIM; k++) s += r20[k] * W1s[k * 128 + c];
            h1s[c * 128 + n] = fmaxf(s, 0.f);
        }
    }
    __syncthreads();

    int tx = tid & 15, ty = tid >> 4;
    float acc[8][8] = {};
    for (int k = 0; k < 128; k++) {
        float4 a0 = *(const float4*)&h1s[k * 128 + ty * 8];
        float4 a1 = *(const float4*)&h1s[k * 128 + ty * 8 + 4];
        float4 w0 = *(const float4*)&W2s[k * 128 + tx * 8];
        float4 w1 = *(const float4*)&W2s[k * 128 + tx * 8 + 4];
        float av[8] = {a0.x, a0.y, a0.z, a0.w, a1.x, a1.y, a1.z, a1.w};
        float wv[8] = {w0.x, w0.y, w0.z, w0.w, w1.x, w1.y, w1.z, w1.w};
#pragma unroll
        for (int i = 0; i < 8; i++)
#pragma unroll
            for (int j = 0; j < 8; j++) acc[i][j] += av[i] * wv[j];
    }
    int c0 = tx * 8;
    float bb[8];
#pragma unroll
    for (int j = 0; j < 8; j++) bb[j] = b2[t * HID + c0 + j];
    for (int i = 0; i < 8; i++) {
        int gi = start + ty * 8 + i;
        if (gi >= cnt) break;
        int node = nl[ty * 8 + i];
        __half2 hi[4], lo[4];
#pragma unroll
        for (int q = 0; q < 4; q++)
            split2h(acc[i][2 * q] + bb[2 * q], acc[i][2 * q + 1] + bb[2 * q + 1], &hi[q], &lo[q]);
        *(float4*)&g_xh[(size_t)node * HID + c0] = *(float4*)hi;
        *(float4*)&g_xl[(size_t)node * HID + c0] = *(float4*)lo;
    }
}

// ---------------- weight prep: B[n][k] = W[k][n], single fp16 ----------------
__global__ void k_prepB(const float* __restrict__ relW, const float* __restrict__ linW) {
    int i = blockIdx.x * blockDim.x + threadIdx.x;
    if (i >= 2 * 512 * 128) return;
    int l = i >> 16;
    int rem = i & 65535;
    int n = rem >> 7, k = rem & 127;
    int jt = n >> 7, c = n & 127;
    float v = (jt < 3) ? relW[(((size_t)l * 3 + jt) * 128 + k) * 128 + c]
                       : linW[((size_t)l * 128 + k) * 128 + c];
    g_Bw[i] = __float2half_rn(v);
}

// ---------------- fp16 mma.sync GEMM, A-resident over 4 col chunks ----------------
// grid (NPAD/128): block = 128 rows; jt loop covers rel0..2 + lin.
// A split fp16 hi/lo (near-exact), B single fp16. 2 MMA passes per k-step.
#define KS 136
#define MMA_SMEM (3 * 128 * KS * 2)

__global__ void __launch_bounds__(256, 1)
k_mma(int l, const float* __restrict__ linb) {
    extern __shared__ __half smh[];
    __half* Ah = smh;
    __half* Al = Ah + 128 * KS;
    __half* Bs = Al + 128 * KS;

    int tid = threadIdx.x;
    int wid = tid >> 5, lane = tid & 31;
    int rowBase = blockIdx.x * 128;

    // load A once (hi+lo)
    for (int i = tid; i < 2048; i += 256) {
        int row = i >> 4, kc = (i & 15) * 8;
        size_t go = (size_t)(rowBase + row) * 128 + kc;
        int so = row * KS + kc;
        *(float4*)&Ah[so] = *(const float4*)&g_xh[go];
        *(float4*)&Al[so] = *(const float4*)&g_xl[go];
    }

    int wm = wid >> 1, wn = wid & 1;
    int g = lane >> 2, tc = lane & 3;

    for (int jt = 0; jt < 4; jt++) {
        const __half* gB = g_Bw + ((size_t)l * 512 + jt * 128) * 128;
        for (int i = tid; i < 2048; i += 256) {
            int row = i >> 4, kc = (i & 15) * 8;
            *(float4*)&Bs[row * KS + kc] = *(const float4*)&gB[(size_t)row * 128 + kc];
        }
        __syncthreads();

        float c[2][8][4];
#pragma unroll
        for (int mt = 0; mt < 2; mt++)
#pragma unroll
            for (int nt = 0; nt < 8; nt++)
#pragma unroll
                for (int q = 0; q < 4; q++) c[mt][nt][q] = 0.f;

#pragma unroll
        for (int p = 0; p < 2; p++) {
            const __half* A = p ? Al : Ah;
#pragma unroll
            for (int k0 = 0; k0 < 8; k0++) {
                int kb = k0 * 16 + tc * 2;
                uint32_t a[2][4];
#pragma unroll
                for (int mt = 0; mt < 2; mt++) {
                    int r0 = wm * 32 + mt * 16 + g;
                    a[mt][0] = *(const uint32_t*)&A[r0 * KS + kb];
                    a[mt][1] = *(const uint32_t*)&A[(r0 + 8) * KS + kb];
                    a[mt][2] = *(const uint32_t*)&A[r0 * KS + kb + 8];
                    a[mt][3] = *(const uint32_t*)&A[(r0 + 8) * KS + kb + 8];
                }
                uint32_t b[8][2];
#pragma unroll
                for (int nt = 0; nt < 8; nt++) {
                    int col = wn * 64 + nt * 8 + g;
                    b[nt][0] = *(const uint32_t*)&Bs[col * KS + kb];
                    b[nt][1] = *(const uint32_t*)&Bs[col * KS + kb + 8];
                }
#pragma unroll
                for (int mt = 0; mt < 2; mt++)
#pragma unroll
                    for (int nt = 0; nt < 8; nt++) {
                        float* cc = c[mt][nt];
                        asm volatile(
                            "mma.sync.aligned.m16n8k16.row.col.f32.f16.f16.f32 "
                            "{%0,%1,%2,%3}, {%4,%5,%6,%7}, {%8,%9}, {%0,%1,%2,%3};"
                            : "+f"(cc[0]), "+f"(cc[1]), "+f"(cc[2]), "+f"(cc[3])
                            : "r"(a[mt][0]), "r"(a[mt][1]), "r"(a[mt][2]), "r"(a[mt][3]),
                              "r"(b[nt][0]), "r"(b[nt][1]));
                    }
            }
        }

        // epilogue for this chunk
#pragma unroll
        for (int mt = 0; mt < 2; mt++) {
            int row0 = rowBase + wm * 32 + mt * 16 + g;
            int row1 = row0 + 8;
#pragma unroll
            for (int nt = 0; nt < 8; nt++) {
                int colLoc = wn * 64 + nt * 8 + tc * 2;
                float* cc = c[mt][nt];
                if (jt < 3) {
                    size_t o0 = (size_t)row0 * 384 + jt * 128 + colLoc;
                    size_t o1 = (size_t)row1 * 384 + jt * 128 + colLoc;
                    if (row0 < NN) *(__half2*)&g_yh[o0] = __floats2half2_rn(cc[0], cc[1]);
                    if (row1 < NN) *(__half2*)&g_yh[o1] = __floats2half2_rn(cc[2], cc[3]);
                } else {
                    float b0 = linb[colLoc], b1 = linb[colLoc + 1];
                    if (row0 < NN)
                        *(float2*)&g_h[(size_t)row0 * 128 + colLoc] = make_float2(cc[0] + b0, cc[1] + b1);
                    if (row1 < NN)
                        *(float2*)&g_h[(size_t)row1 * 128 + colLoc] = make_float2(cc[2] + b0, cc[3] + b1);
                }
            }
        }
        __syncthreads();   // B reused next jt
    }
}

// ---------------- fused CSR aggregation + LayerNorm ----------------
// mode 0 (layer 1): write fp16 hi/lo x for next GEMM
// mode 1 (layer 2): block-reduce LN output straight into g_pool
__global__ void __launch_bounds__(256)
k_aggr_ln(const float* __restrict__ gg, const float* __restrict__ gb, int mode) {
    __shared__ float shp[8][128];
    int warp = threadIdx.x >> 5, lane = threadIdx.x & 31;
    int node = blockIdx.x * 8 + warp;
    bool live = node < NN;
    float4 o = make_float4(0.f, 0.f, 0.f, 0.f);
    int c = lane * 4;

    if (live) {
        int base = g_roff[node];
        int cnt  = g_cnt[node];

        float a0 = 0.f, a1 = 0.f, a2 = 0.f, a3 = 0.f;
        for (int j0 = 0; j0 < cnt; j0 += 8) {
            int v[8];
            uint2 u[8];
#pragma unroll
            for (int q = 0; q < 8; q++)
                v[q] = (j0 + q < cnt) ? __ldg(&g_csr[base + j0 + q]) : -1;
#pragma unroll
            for (int q = 0; q < 8; q++) {
                if (v[q] >= 0) {
                    int s = v[q] >> 2, r = v[q] & 3;
                    u[q] = *(const uint2*)&g_yh[((size_t)s * NREL + r) * HID + c];
                } else {
                    u[q] = make_uint2(0u, 0u);
                }
            }
#pragma unroll
            for (int q = 0; q < 8; q++) {
                float2 f0 = __half22float2(*(__half2*)&u[q].x);
                float2 f1 = __half22float2(*(__half2*)&u[q].y);
                a0 += f0.x; a1 += f0.y; a2 += f1.x; a3 += f1.y;
            }
        }
        float di = 1.0f / fmaxf((float)cnt, 1.0f);

        float4 hv = *(const float4*)&g_h[(size_t)node * HID + c];
        hv.x += a0 * di; hv.y += a1 * di; hv.z += a2 * di; hv.w += a3 * di;

        float s = hv.x + hv.y + hv.z + hv.w;
#pragma unroll
        for (int of = 16; of; of >>= 1) s += __shfl_xor_sync(0xFFFFFFFFu, s, of);
        float mu = s * (1.0f / HID);
        float dx = hv.x - mu, dy = hv.y - mu, dz = hv.z - mu, dw = hv.w - mu;
        float s2 = dx * dx + dy * dy + dz * dz + dw * dw;
#pragma unroll
        for (int of = 16; of; of >>= 1) s2 += __shfl_xor_sync(0xFFFFFFFFu, s2, of);
        float rs = rsqrtf(s2 * (1.0f / HID) + LN_EPS);

        float4 g4 = *(const float4*)&gg[c];
        float4 b4 = *(const float4*)&gb[c];
        o = make_float4(dx * rs * g4.x + b4.x, dy * rs * g4.y + b4.y,
                        dz * rs * g4.z + b4.z, dw * rs * g4.w + b4.w);
    }

    if (mode == 0) {
        if (live) {
            __half2 hi0, lo0, hi1, lo1;
            split2h(o.x, o.y, &hi0, &lo0);
            split2h(o.z, o.w, &hi1, &lo1);
            *(float2*)&g_xh[(size_t)node * HID + c] =
                make_float2(__uint_as_float(*(uint32_t*)&hi0), __uint_as_float(*(uint32_t*)&hi1));
            *(float2*)&g_xl[(size_t)node * HID + c] =
                make_float2(__uint_as_float(*(uint32_t*)&lo0), __uint_as_float(*(uint32_t*)&lo1));
        }
    } else {
        shp[warp][c]     = o.x;
        shp[warp][c + 1] = o.y;
        shp[warp][c + 2] = o.z;
        shp[warp][c + 3] = o.w;
        __syncthreads();
        if (threadIdx.x < 128) {
            float s = 0.f;
#pragma unroll
            for (int w = 0; w < 8; w++) s += shp[w][threadIdx.x];
            atomicAdd(&g_pool[threadIdx.x], s);
        }
    }
}

// ---------------- regressor ----------------
__global__ void k_final(const float* __restrict__ regW, const float* __restrict__ regb,
                        float* __restrict__ out) {
    int c = threadIdx.x;
    __shared__ float red[HID];
    red[c] = g_pool[c] * (1.0f / NN) * regW[c];
    __syncthreads();
    for (int s = 64; s; s >>= 1) {
        if (c < s) red[c] += red[c + s];
        __syncthreads();
    }
    if (c == 0) out[0] = red[0] + regb[0];
}

// ---------------- launch ----------------
extern "C" void kernel_launch(void* const* d_in, const int* in_sizes, int n_in,
                              void* d_out, int out_size) {
    const int*   z     = (const int*)d_in[0];
    const float* sd    = (const float*)d_in[1];
    const float* dfp   = (const float*)d_in[2];
    const float* cond  = (const float*)d_in[3];
    const float* mult  = (const float*)d_in[4];
    const int*   ntype = (const int*)d_in[5];
    const int*   eidx  = (const int*)d_in[6];
    const int*   etyp  = (const int*)d_in[7];
    const float* zemb  = (const float*)d_in[8];
    const float* eW1   = (const float*)d_in[9];
    const float* eb1   = (const float*)d_in[10];
    const float* eW2   = (const float*)d_in[11];
    const float* eb2   = (const float*)d_in[12];
    const float* linW  = (const float*)d_in[13];
    const float* linb  = (const float*)d_in[14];
    const float* relW  = (const float*)d_in[15];
    const float* lng   = (const float*)d_in[16];
    const float* lnb   = (const float*)d_in[17];
    const float* regW  = (const float*)d_in[18];
    const float* regb  = (const float*)d_in[19];
    float* out = (float*)d_out;

    cudaFuncSetAttribute(k_encoder, cudaFuncAttributeMaxDynamicSharedMemorySize, ENC_SMEM);
    cudaFuncSetAttribute(k_mma, cudaFuncAttributeMaxDynamicSharedMemorySize, MMA_SMEM);

    const int rowBlocks = NPAD / 128;   // 782

    k_init<<<(NN + 255) / 256, 256>>>();
    k_bucket<<<(NN + 255) / 256, 256>>>(ntype);
    k_cnt<<<(EE + 255) / 256, 256>>>(eidx + EE);
    k_scan1<<<(NN + 255) / 256, 256>>>();
    k_scan2<<<1, 512>>>();
    k_scan3<<<(NN + 255) / 256, 256>>>();
    k_fill<<<(EE + 255) / 256, 256>>>(eidx, eidx + EE, etyp);
    k_encoder<<<dim3(rowBlocks, NTYPE), 256, ENC_SMEM>>>(z, sd, dfp, cond, mult,
                                                         zemb, eW1, eb1, eW2, eb2);
    k_prepB<<<512, 256>>>(relW, linW);
    for (int l = 0; l < 2; l++) {
        k_mma<<<rowBlocks, 256, MMA_SMEM>>>(l, linb + l * HID);
        k_aggr_ln<<<(NN + 7) / 8, 256>>>(lng + l * HID, lnb + l * HID, l);
    }
    k_final<<<1, 128>>>(regW, regb, out);
}

// round 6
// speedup vs baseline: 3.3417x; 1.3177x over previous
#include <cuda_runtime.h>
#include <cuda_fp16.h>
#include <cstdint>

#define NN    100000
#define NPAD  100096
#define EE    1600000
#define HID   128
#define INDIM 20
#define NREL  3
#define NTYPE 4
#define LN_EPS 1e-5f

// ---------------- device scratch (no allocs allowed) ----------------
static __device__ float  g_h[(size_t)NN * HID];            // x@lin + b (pre-agg)
static __device__ __half g_yh[(size_t)NN * NREL * HID];    // per-relation feats fp16 (76.8MB)
static __device__ __half g_xh[(size_t)NPAD * HID];         // x (fp16); pad rows stay 0
static __device__ __half g_Bw[2 * 512 * 128];              // weights B[n][k] fp16, per layer
static __device__ int    g_cnt[NN];
static __device__ int    g_roff[NN];
static __device__ int    g_cur[NN];
static __device__ int    g_csr[EE];                        // (src<<2)|etype, grouped by dst
static __device__ int    g_bsum[512];
static __device__ int    g_tlist[(size_t)NTYPE * NN];
static __device__ int    g_tcount[NTYPE];
static __device__ float  g_pool[HID];

// ---------------- init / bucketing / CSR build ----------------
__global__ void k_init2() {
    int i = blockIdx.x * blockDim.x + threadIdx.x;
    if (i < NN) { g_cnt[i] = 0; g_cur[i] = 0; }
    if (i < HID) g_pool[i] = 0.f;
    if (i < 512) g_bsum[i] = 0;
}

__global__ void k_bucket(const int* __restrict__ ntype) {
    int i = blockIdx.x * blockDim.x + threadIdx.x;
    if (i >= NN) return;
    int t = ntype[i];
    int pos = atomicAdd(&g_tcount[t], 1);
    g_tlist[(size_t)t * NN + pos] = i;
}

__global__ void k_cnt(const int* __restrict__ dst) {
    int e = blockIdx.x * blockDim.x + threadIdx.x;
    if (e >= EE) return;
    atomicAdd(&g_cnt[dst[e]], 1);
}

__global__ void k_scan1() {
    __shared__ int sh[256];
    int i = blockIdx.x * 256 + threadIdx.x;
    int v = (i < NN) ? g_cnt[i] : 0;
    sh[threadIdx.x] = v;
    __syncthreads();
    for (int o = 1; o < 256; o <<= 1) {
        int t = (threadIdx.x >= o) ? sh[threadIdx.x - o] : 0;
        __syncthreads();
        sh[threadIdx.x] += t;
        __syncthreads();
    }
    if (i < NN) g_roff[i] = sh[threadIdx.x] - v;
    if (threadIdx.x == 255) g_bsum[blockIdx.x] = sh[255];
}

__global__ void k_scan2() {
    __shared__ int sh[512];
    int t = threadIdx.x;
    int v = g_bsum[t];
    sh[t] = v;
    __syncthreads();
    for (int o = 1; o < 512; o <<= 1) {
        int u = (t >= o) ? sh[t - o] : 0;
        __syncthreads();
        sh[t] += u;
        __syncthreads();
    }
    g_bsum[t] = sh[t] - v;
}

__global__ void k_scan3() {
    int i = blockIdx.x * blockDim.x + threadIdx.x;
    if (i >= NN) return;
    g_roff[i] += g_bsum[i >> 8];
}

__global__ void k_fill(const int* __restrict__ src, const int* __restrict__ dst,
                       const int* __restrict__ etyp) {
    int e = blockIdx.x * blockDim.x + threadIdx.x;
    if (e >= EE) return;
    int d = dst[e];
    int pos = g_roff[d] + atomicAdd(&g_cur[d], 1);
    g_csr[pos] = (src[e] << 2) | etyp[e];
}

// ---------------- weight prep: B[n][k] = W[k][n], single fp16 (+clear tcount) ----------------
__global__ void k_prepB(const float* __restrict__ relW, const float* __restrict__ linW) {
    int i = blockIdx.x * blockDim.x + threadIdx.x;
    if (i < NTYPE) g_tcount[i] = 0;
    if (i >= 2 * 512 * 128) return;
    int l = i >> 16;
    int rem = i & 65535;
    int n = rem >> 7, k = rem & 127;
    int jt = n >> 7, c = n & 127;
    float v = (jt < 3) ? relW[(((size_t)l * 3 + jt) * 128 + k) * 128 + c]
                       : linW[((size_t)l * 128 + k) * 128 + c];
    g_Bw[i] = __float2half_rn(v);
}

// ---------------- type-specific encoder: stage1 SIMT, stage2 fp16 MMA ----------------
#define EKS 136
// bytes: W1s(2560f) + raws(2688f) + Ah(128*EKS h) + Bs(128*EKS h)
#define ENC_SMEM (2560 * 4 + 2688 * 4 + 2 * 128 * EKS * 2)

__global__ void __launch_bounds__(256, 1)
k_encoder(const int* __restrict__ z, const float* __restrict__ sd,
          const float* __restrict__ dfp, const float* __restrict__ cond,
          const float* __restrict__ mult, const float* __restrict__ zemb,
          const float* __restrict__ W1, const float* __restrict__ b1,
          const float* __restrict__ W2, const float* __restrict__ b2) {
    int t = blockIdx.y;
    int cnt = g_tcount[t];
    int start = blockIdx.x * 128;
    if (start >= cnt) return;

    extern __shared__ char smc[];
    float*  W1s  = (float*)smc;                       // [20][128]
    float*  raws = W1s + 2560;                        // [128][21]
    __half* Ah   = (__half*)(raws + 2688);            // [128 n][EKS]
    __half* Bs   = Ah + 128 * EKS;                    // [128 c][EKS]  (W2 col-major)
    __shared__ int nl[128];

    int tid = threadIdx.x;
    if (tid < 128) {
        int idx = start + tid;
        nl[tid] = g_tlist[(size_t)t * NN + (idx < cnt ? idx : cnt - 1)];
    }
    for (int i = tid; i < 640; i += 256)
        *(float4*)&W1s[i * 4] = *(const float4*)&W1[(size_t)t * 2560 + i * 4];
    // W2 [k][c] -> Bs[c][k] fp16 transpose
    for (int i = tid; i < 4096; i += 256) {
        int k = i >> 5, c4 = (i & 31) * 4;
        float4 w = *(const float4*)&W2[(size_t)t * 16384 + k * 128 + c4];
        Bs[(c4 + 0) * EKS + k] = __float2half_rn(w.x);
        Bs[(c4 + 1) * EKS + k] = __float2half_rn(w.y);
        Bs[(c4 + 2) * EKS + k] = __float2half_rn(w.z);
        Bs[(c4 + 3) * EKS + k] = __float2half_rn(w.w);
    }
    __syncthreads();

    for (int i = tid; i < 128 * INDIM; i += 256) {
        int n = i / INDIM, k = i % INDIM;
        int node = nl[n];
        float v;
        if (k < 16)       v = zemb[(size_t)z[node] * 16 + k];
        else if (k == 16) v = sd[node];
        else if (k == 17) v = dfp[node];
        else if (k == 18) v = cond[node];
        else              v = mult[node];
        raws[n * 21 + k] = v;
    }
    __syncthreads();

    // stage 1: Ah[n][c] = relu(raw[n].W1[:,c] + b1[c]) as fp16
    {
        int n = tid & 127;
        float r20[INDIM];
#pragma unroll
        for (int k = 0; k < INDIM; k++) r20[k] = raws[n * 21 + k];
        int chalf = tid >> 7;
        for (int p = 0; p < 64; p++) {
            int c = chalf + p * 2;
            float s = b1[t * HID + c];
#pragma unroll
            for (int k = 0; k < INDIM; k++) s += r20[k] * W1s[k * 128 + c];
            Ah[n * EKS + c] = __float2half_rn(fmaxf(s, 0.f));
        }
    }
    __syncthreads();

    // stage 2: out = Ah @ Bs^T (+b2) via mma.sync; 8 warps: 4(m) x 2(n)
    int wid = tid >> 5, lane = tid & 31;
    int wm = wid >> 1, wn = wid & 1;
    int g = lane >> 2, tc = lane & 3;

    float c[2][8][4];
#pragma unroll
    for (int mt = 0; mt < 2; mt++)
#pragma unroll
        for (int nt = 0; nt < 8; nt++)
#pragma unroll
            for (int q = 0; q < 4; q++) c[mt][nt][q] = 0.f;

#pragma unroll
    for (int k0 = 0; k0 < 8; k0++) {
        int kb = k0 * 16 + tc * 2;
        uint32_t a[2][4];
#pragma unroll
        for (int mt = 0; mt < 2; mt++) {
            int r0 = wm * 32 + mt * 16 + g;
            a[mt][0] = *(const uint32_t*)&Ah[r0 * EKS + kb];
            a[mt][1] = *(const uint32_t*)&Ah[(r0 + 8) * EKS + kb];
            a[mt][2] = *(const uint32_t*)&Ah[r0 * EKS + kb + 8];
            a[mt][3] = *(const uint32_t*)&Ah[(r0 + 8) * EKS + kb + 8];
        }
        uint32_t b[8][2];
#pragma unroll
        for (int nt = 0; nt < 8; nt++) {
            int col = wn * 64 + nt * 8 + g;
            b[nt][0] = *(const uint32_t*)&Bs[col * EKS + kb];
            b[nt][1] = *(const uint32_t*)&Bs[col * EKS + kb + 8];
        }
#pragma unroll
        for (int mt = 0; mt < 2; mt++)
#pragma unroll
            for (int nt = 0; nt < 8; nt++) {
                float* cc = c[mt][nt];
                asm volatile(
                    "mma.sync.aligned.m16n8k16.row.col.f32.f16.f16.f32 "
                    "{%0,%1,%2,%3}, {%4,%5,%6,%7}, {%8,%9}, {%0,%1,%2,%3};"
                    : "+f"(cc[0]), "+f"(cc[1]), "+f"(cc[2]), "+f"(cc[3])
                    : "r"(a[mt][0]), "r"(a[mt][1]), "r"(a[mt][2]), "r"(a[mt][3]),
                      "r"(b[nt][0]), "r"(b[nt][1]));
            }
    }

#pragma unroll
    for (int mt = 0; mt < 2; mt++) {
        int lr0 = wm * 32 + mt * 16 + g;
        int lr1 = lr0 + 8;
#pragma unroll
        for (int nt = 0; nt < 8; nt++) {
            int colLoc = wn * 64 + nt * 8 + tc * 2;
            float* cc = c[mt][nt];
            float b0 = b2[t * HID + colLoc], b1v = b2[t * HID + colLoc + 1];
            if (start + lr0 < cnt)
                *(__half2*)&g_xh[(size_t)nl[lr0] * HID + colLoc] =
                    __floats2half2_rn(cc[0] + b0, cc[1] + b1v);
            if (start + lr1 < cnt)
                *(__half2*)&g_xh[(size_t)nl[lr1] * HID + colLoc] =
                    __floats2half2_rn(cc[2] + b0, cc[3] + b1v);
        }
    }
}

// ---------------- fp16 mma.sync GEMM, A-resident over 4 col chunks ----------------
#define KS 136
#define MMA_SMEM (2 * 128 * KS * 2)

__global__ void __launch_bounds__(256, 2)
k_mma(int l, const float* __restrict__ linb) {
    extern __shared__ __half smh[];
    __half* Ah = smh;
    __half* Bs = Ah + 128 * KS;

    int tid = threadIdx.x;
    int wid = tid >> 5, lane = tid & 31;
    int rowBase = blockIdx.x * 128;

    for (int i = tid; i < 2048; i += 256) {
        int row = i >> 4, kc = (i & 15) * 8;
        *(float4*)&Ah[row * KS + kc] = *(const float4*)&g_xh[(size_t)(rowBase + row) * 128 + kc];
    }

    int wm = wid >> 1, wn = wid & 1;
    int g = lane >> 2, tc = lane & 3;

    for (int jt = 0; jt < 4; jt++) {
        const __half* gB = g_Bw + ((size_t)l * 512 + jt * 128) * 128;
        for (int i = tid; i < 2048; i += 256) {
            int row = i >> 4, kc = (i & 15) * 8;
            *(float4*)&Bs[row * KS + kc] = *(const float4*)&gB[(size_t)row * 128 + kc];
        }
        __syncthreads();

        float c[2][8][4];
#pragma unroll
        for (int mt = 0; mt < 2; mt++)
#pragma unroll
            for (int nt = 0; nt < 8; nt++)
#pragma unroll
                for (int q = 0; q < 4; q++) c[mt][nt][q] = 0.f;

#pragma unroll
        for (int k0 = 0; k0 < 8; k0++) {
            int kb = k0 * 16 + tc * 2;
            uint32_t a[2][4];
#pragma unroll
            for (int mt = 0; mt < 2; mt++) {
                int r0 = wm * 32 + mt * 16 + g;
                a[mt][0] = *(const uint32_t*)&Ah[r0 * KS + kb];
                a[mt][1] = *(const uint32_t*)&Ah[(r0 + 8) * KS + kb];
                a[mt][2] = *(const uint32_t*)&Ah[r0 * KS + kb + 8];
                a[mt][3] = *(const uint32_t*)&Ah[(r0 + 8) * KS + kb + 8];
            }
            uint32_t b[8][2];
#pragma unroll
            for (int nt = 0; nt < 8; nt++) {
                int col = wn * 64 + nt * 8 + g;
                b[nt][0] = *(const uint32_t*)&Bs[col * KS + kb];
                b[nt][1] = *(const uint32_t*)&Bs[col * KS + kb + 8];
            }
#pragma unroll
            for (int mt = 0; mt < 2; mt++)
#pragma unroll
                for (int nt = 0; nt < 8; nt++) {
                    float* cc = c[mt][nt];
                    asm volatile(
                        "mma.sync.aligned.m16n8k16.row.col.f32.f16.f16.f32 "
                        "{%0,%1,%2,%3}, {%4,%5,%6,%7}, {%8,%9}, {%0,%1,%2,%3};"
                        : "+f"(cc[0]), "+f"(cc[1]), "+f"(cc[2]), "+f"(cc[3])
                        : "r"(a[mt][0]), "r"(a[mt][1]), "r"(a[mt][2]), "r"(a[mt][3]),
                          "r"(b[nt][0]), "r"(b[nt][1]));
                }
        }

#pragma unroll
        for (int mt = 0; mt < 2; mt++) {
            int row0 = rowBase + wm * 32 + mt * 16 + g;
            int row1 = row0 + 8;
#pragma unroll
            for (int nt = 0; nt < 8; nt++) {
                int colLoc = wn * 64 + nt * 8 + tc * 2;
                float* cc = c[mt][nt];
                if (jt < 3) {
                    size_t o0 = (size_t)row0 * 384 + jt * 128 + colLoc;
                    size_t o1 = (size_t)row1 * 384 + jt * 128 + colLoc;
                    if (row0 < NN) *(__half2*)&g_yh[o0] = __floats2half2_rn(cc[0], cc[1]);
                    if (row1 < NN) *(__half2*)&g_yh[o1] = __floats2half2_rn(cc[2], cc[3]);
                } else {
                    float b0 = linb[colLoc], b1 = linb[colLoc + 1];
                    if (row0 < NN)
                        *(float2*)&g_h[(size_t)row0 * 128 + colLoc] = make_float2(cc[0] + b0, cc[1] + b1);
                    if (row1 < NN)
                        *(float2*)&g_h[(size_t)row1 * 128 + colLoc] = make_float2(cc[2] + b0, cc[3] + b1);
                }
            }
        }
        __syncthreads();
    }
}

// ---------------- fused CSR aggregation + LayerNorm ----------------
__global__ void __launch_bounds__(256)
k_aggr_ln(const float* __restrict__ gg, const float* __restrict__ gb, int mode) {
    __shared__ float shp[8][128];
    int warp = threadIdx.x >> 5, lane = threadIdx.x & 31;
    int node = blockIdx.x * 8 + warp;
    bool live = node < NN;
    float4 o = make_float4(0.f, 0.f, 0.f, 0.f);
    int c = lane * 4;

    if (live) {
        int base = g_roff[node];
        int cnt  = g_cnt[node];

        float a0 = 0.f, a1 = 0.f, a2 = 0.f, a3 = 0.f;
        for (int j0 = 0; j0 < cnt; j0 += 8) {
            int v[8];
            uint2 u[8];
#pragma unroll
            for (int q = 0; q < 8; q++)
                v[q] = (j0 + q < cnt) ? __ldg(&g_csr[base + j0 + q]) : -1;
#pragma unroll
            for (int q = 0; q < 8; q++) {
                if (v[q] >= 0) {
                    int s = v[q] >> 2, r = v[q] & 3;
                    u[q] = *(const uint2*)&g_yh[((size_t)s * NREL + r) * HID + c];
                } else {
                    u[q] = make_uint2(0u, 0u);
                }
            }
#pragma unroll
            for (int q = 0; q < 8; q++) {
                float2 f0 = __half22float2(*(__half2*)&u[q].x);
                float2 f1 = __half22float2(*(__half2*)&u[q].y);
                a0 += f0.x; a1 += f0.y; a2 += f1.x; a3 += f1.y;
            }
        }
        float di = 1.0f / fmaxf((float)cnt, 1.0f);

        float4 hv = *(const float4*)&g_h[(size_t)node * HID + c];
        hv.x += a0 * di; hv.y += a1 * di; hv.z += a2 * di; hv.w += a3 * di;

        float s = hv.x + hv.y + hv.z + hv.w;
#pragma unroll
        for (int of = 16; of; of >>= 1) s += __shfl_xor_sync(0xFFFFFFFFu, s, of);
        float mu = s * (1.0f / HID);
        float dx = hv.x - mu, dy = hv.y - mu, dz = hv.z - mu, dw = hv.w - mu;
        float s2 = dx * dx + dy * dy + dz * dz + dw * dw;
#pragma unroll
        for (int of = 16; of; of >>= 1) s2 += __shfl_xor_sync(0xFFFFFFFFu, s2, of);
        float rs = rsqrtf(s2 * (1.0f / HID) + LN_EPS);

        float4 g4 = *(const float4*)&gg[c];
        float4 b4 = *(const float4*)&gb[c];
        o = make_float4(dx * rs * g4.x + b4.x, dy * rs * g4.y + b4.y,
                        dz * rs * g4.z + b4.z, dw * rs * g4.w + b4.w);
    }

    if (mode == 0) {
        if (live) {
            __half2 h0 = __floats2half2_rn(o.x, o.y);
            __half2 h1 = __floats2half2_rn(o.z, o.w);
            *(float2*)&g_xh[(size_t)node * HID + c] =
                make_float2(__uint_as_float(*(uint32_t*)&h0), __uint_as_float(*(uint32_t*)&h1));
        }
    } else {
        shp[warp][c]     = o.x;
        shp[warp][c + 1] = o.y;
        shp[warp][c + 2] = o.z;
        shp[warp][c + 3] = o.w;
        __syncthreads();
        if (threadIdx.x < 128) {
            float s = 0.f;
#pragma unroll
            for (int w = 0; w < 8; w++) s += shp[w][threadIdx.x];
            atomicAdd(&g_pool[threadIdx.x], s);
        }
    }
}

// ---------------- regressor ----------------
__global__ void k_final(const float* __restrict__ regW, const float* __restrict__ regb,
                        float* __restrict__ out) {
    int c = threadIdx.x;
    __shared__ float red[HID];
    red[c] = g_pool[c] * (1.0f / NN) * regW[c];
    __syncthreads();
    for (int s = 64; s; s >>= 1) {
        if (c < s) red[c] += red[c + s];
        __syncthreads();
    }
    if (c == 0) out[0] = red[0] + regb[0];
}

// ---------------- launch ----------------
extern "C" void kernel_launch(void* const* d_in, const int* in_sizes, int n_in,
                              void* d_out, int out_size) {
    const int*   z     = (const int*)d_in[0];
    const float* sd    = (const float*)d_in[1];
    const float* dfp   = (const float*)d_in[2];
    const float* cond  = (const float*)d_in[3];
    const float* mult  = (const float*)d_in[4];
    const int*   ntype = (const int*)d_in[5];
    const int*   eidx  = (const int*)d_in[6];
    const int*   etyp  = (const int*)d_in[7];
    const float* zemb  = (const float*)d_in[8];
    const float* eW1   = (const float*)d_in[9];
    const float* eb1   = (const float*)d_in[10];
    const float* eW2   = (const float*)d_in[11];
    const float* eb2   = (const float*)d_in[12];
    const float* linW  = (const float*)d_in[13];
    const float* linb  = (const float*)d_in[14];
    const float* relW  = (const float*)d_in[15];
    const float* lng   = (const float*)d_in[16];
    const float* lnb   = (const float*)d_in[17];
    const float* regW  = (const float*)d_in[18];
    const float* regb  = (const float*)d_in[19];
    float* out = (float*)d_out;

    cudaFuncSetAttribute(k_encoder, cudaFuncAttributeMaxDynamicSharedMemorySize, ENC_SMEM);
    cudaFuncSetAttribute(k_mma, cudaFuncAttributeMaxDynamicSharedMemorySize, MMA_SMEM);

    const int rowBlocks = NPAD / 128;   // 782

    // order chosen so launch #4 (ncu capture) is k_mma layer 0
    k_prepB<<<512, 256>>>(relW, linW);                       // 1 (also clears tcount)
    k_bucket<<<(NN + 255) / 256, 256>>>(ntype);              // 2
    k_encoder<<<dim3(rowBlocks, NTYPE), 256, ENC_SMEM>>>(    // 3
        z, sd, dfp, cond, mult, zemb, eW1, eb1, eW2, eb2);
    k_mma<<<rowBlocks, 256, MMA_SMEM>>>(0, linb);            // 4  <-- ncu
    k_init2<<<(NN + 255) / 256, 256>>>();                    // 5
    k_cnt<<<(EE + 255) / 256, 256>>>(eidx + EE);             // 6
    k_scan1<<<(NN + 255) / 256, 256>>>();                    // 7
    k_scan2<<<1, 512>>>();                                   // 8
    k_scan3<<<(NN + 255) / 256, 256>>>();                    // 9
    k_fill<<<(EE + 255) / 256, 256>>>(eidx, eidx + EE, etyp);// 10
    k_aggr_ln<<<(NN + 7) / 8, 256>>>(lng, lnb, 0);           // 11
    k_mma<<<rowBlocks, 256, MMA_SMEM>>>(1, linb + HID);      // 12
    k_aggr_ln<<<(NN + 7) / 8, 256>>>(lng + HID, lnb + HID, 1); // 13
    k_final<<<1, 128>>>(regW, regb, out);                    // 14
}

// round 7
// speedup vs baseline: 3.4461x; 1.0312x over previous
#include <cuda_runtime.h>
#include <cuda_fp16.h>
#include <cstdint>

#define NN    100000
#define NPAD  100096
#define EE    1600000
#define HID   128
#define INDIM 20
#define NREL  3
#define NTYPE 4
#define LN_EPS 1e-5f

// ---------------- device scratch (no allocs allowed) ----------------
static __device__ float  g_h[(size_t)NN * HID];            // x@lin + b (pre-agg)
static __device__ __half g_yh[(size_t)NN * NREL * HID];    // per-relation feats fp16 (76.8MB)
static __device__ __half g_xh[(size_t)NPAD * HID];         // x (fp16); pad rows stay 0
static __device__ __half g_Bw[2 * 512 * 128];              // weights B[n][k] fp16, per layer
static __device__ int    g_cnt[NN];
static __device__ int    g_roff[NN];
static __device__ int    g_cur[NN];
static __device__ int    g_csr[EE];                        // (src<<2)|etype, grouped by dst
static __device__ int    g_bsum[512];
static __device__ int    g_tlist[(size_t)NTYPE * NN];
static __device__ int    g_tcount[NTYPE];
static __device__ float  g_pool[HID];

__device__ __forceinline__ void ldsm4(uint32_t* r, uint32_t a) {
    asm volatile("ldmatrix.sync.aligned.m8n8.x4.shared.b16 {%0,%1,%2,%3}, [%4];"
                 : "=r"(r[0]), "=r"(r[1]), "=r"(r[2]), "=r"(r[3]) : "r"(a));
}
__device__ __forceinline__ void cpa16(uint32_t s, const void* g) {
    asm volatile("cp.async.cg.shared.global [%0], [%1], 16;" :: "r"(s), "l"(g));
}

// ---------------- init / bucketing / CSR build ----------------
__global__ void k_init2() {
    int i = blockIdx.x * blockDim.x + threadIdx.x;
    if (i < NN) { g_cnt[i] = 0; g_cur[i] = 0; }
    if (i < HID) g_pool[i] = 0.f;
    if (i < 512) g_bsum[i] = 0;
}

__global__ void k_bucket(const int* __restrict__ ntype) {
    int i = blockIdx.x * blockDim.x + threadIdx.x;
    if (i >= NN) return;
    int t = ntype[i];
    int pos = atomicAdd(&g_tcount[t], 1);
    g_tlist[(size_t)t * NN + pos] = i;
}

__global__ void k_cnt(const int* __restrict__ dst) {
    int e = blockIdx.x * blockDim.x + threadIdx.x;
    if (e >= EE) return;
    atomicAdd(&g_cnt[dst[e]], 1);
}

__global__ void k_scan1() {
    __shared__ int sh[256];
    int i = blockIdx.x * 256 + threadIdx.x;
    int v = (i < NN) ? g_cnt[i] : 0;
    sh[threadIdx.x] = v;
    __syncthreads();
    for (int o = 1; o < 256; o <<= 1) {
        int t = (threadIdx.x >= o) ? sh[threadIdx.x - o] : 0;
        __syncthreads();
        sh[threadIdx.x] += t;
        __syncthreads();
    }
    if (i < NN) g_roff[i] = sh[threadIdx.x] - v;
    if (threadIdx.x == 255) g_bsum[blockIdx.x] = sh[255];
}

__global__ void k_scan2() {
    __shared__ int sh[512];
    int t = threadIdx.x;
    int v = g_bsum[t];
    sh[t] = v;
    __syncthreads();
    for (int o = 1; o < 512; o <<= 1) {
        int u = (t >= o) ? sh[t - o] : 0;
        __syncthreads();
        sh[t] += u;
        __syncthreads();
    }
    g_bsum[t] = sh[t] - v;
}

__global__ void k_scan3() {
    int i = blockIdx.x * blockDim.x + threadIdx.x;
    if (i >= NN) return;
    g_roff[i] += g_bsum[i >> 8];
}

__global__ void k_fill(const int* __restrict__ src, const int* __restrict__ dst,
                       const int* __restrict__ etyp) {
    int e = blockIdx.x * blockDim.x + threadIdx.x;
    if (e >= EE) return;
    int d = dst[e];
    int pos = g_roff[d] + atomicAdd(&g_cur[d], 1);
    g_csr[pos] = (src[e] << 2) | etyp[e];
}

// ---------------- weight prep: B[n][k] = W[k][n], single fp16 (+clear tcount) ----------------
__global__ void k_prepB(const float* __restrict__ relW, const float* __restrict__ linW) {
    int i = blockIdx.x * blockDim.x + threadIdx.x;
    if (i < NTYPE) g_tcount[i] = 0;
    if (i >= 2 * 512 * 128) return;
    int l = i >> 16;
    int rem = i & 65535;
    int n = rem >> 7, k = rem & 127;
    int jt = n >> 7, c = n & 127;
    float v = (jt < 3) ? relW[(((size_t)l * 3 + jt) * 128 + k) * 128 + c]
                       : linW[((size_t)l * 128 + k) * 128 + c];
    g_Bw[i] = __float2half_rn(v);
}

// ---------------- type-specific encoder: stage1 SIMT, stage2 fp16 MMA ----------------
#define EKS 136
#define ENC_SMEM (2560 * 4 + 2688 * 4 + 2 * 128 * EKS * 2)

__global__ void __launch_bounds__(256, 1)
k_encoder(const int* __restrict__ z, const float* __restrict__ sd,
          const float* __restrict__ dfp, const float* __restrict__ cond,
          const float* __restrict__ mult, const float* __restrict__ zemb,
          const float* __restrict__ W1, const float* __restrict__ b1,
          const float* __restrict__ W2, const float* __restrict__ b2) {
    int t = blockIdx.y;
    int cnt = g_tcount[t];
    int start = blockIdx.x * 128;
    if (start >= cnt) return;

    extern __shared__ char smc[];
    float*  W1s  = (float*)smc;
    float*  raws = W1s + 2560;
    __half* Ah   = (__half*)(raws + 2688);
    __half* Bs   = Ah + 128 * EKS;
    __shared__ int nl[128];

    int tid = threadIdx.x;
    if (tid < 128) {
        int idx = start + tid;
        nl[tid] = g_tlist[(size_t)t * NN + (idx < cnt ? idx : cnt - 1)];
    }
    for (int i = tid; i < 640; i += 256)
        *(float4*)&W1s[i * 4] = *(const float4*)&W1[(size_t)t * 2560 + i * 4];
    for (int i = tid; i < 4096; i += 256) {
        int k = i >> 5, c4 = (i & 31) * 4;
        float4 w = *(const float4*)&W2[(size_t)t * 16384 + k * 128 + c4];
        Bs[(c4 + 0) * EKS + k] = __float2half_rn(w.x);
        Bs[(c4 + 1) * EKS + k] = __float2half_rn(w.y);
        Bs[(c4 + 2) * EKS + k] = __float2half_rn(w.z);
        Bs[(c4 + 3) * EKS + k] = __float2half_rn(w.w);
    }
    __syncthreads();

    for (int i = tid; i < 128 * INDIM; i += 256) {
        int n = i / INDIM, k = i % INDIM;
        int node = nl[n];
        float v;
        if (k < 16)       v = zemb[(size_t)z[node] * 16 + k];
        else if (k == 16) v = sd[node];
        else if (k == 17) v = dfp[node];
        else if (k == 18) v = cond[node];
        else              v = mult[node];
        raws[n * 21 + k] = v;
    }
    __syncthreads();

    {
        int n = tid & 127;
        float r20[INDIM];
#pragma unroll
        for (int k = 0; k < INDIM; k++) r20[k] = raws[n * 21 + k];
        int chalf = tid >> 7;
        for (int p = 0; p < 64; p++) {
            int c = chalf + p * 2;
            float s = b1[t * HID + c];
#pragma unroll
            for (int k = 0; k < INDIM; k++) s += r20[k] * W1s[k * 128 + c];
            Ah[n * EKS + c] = __float2half_rn(fmaxf(s, 0.f));
        }
    }
    __syncthreads();

    int wid = tid >> 5, lane = tid & 31;
    int wm = wid >> 1, wn = wid & 1;
    int g = lane >> 2, tc = lane & 3;

    float c[2][8][4];
#pragma unroll
    for (int mt = 0; mt < 2; mt++)
#pragma unroll
        for (int nt = 0; nt < 8; nt++)
#pragma unroll
            for (int q = 0; q < 4; q++) c[mt][nt][q] = 0.f;

#pragma unroll
    for (int k0 = 0; k0 < 8; k0++) {
        int kb = k0 * 16 + tc * 2;
        uint32_t a[2][4];
#pragma unroll
        for (int mt = 0; mt < 2; mt++) {
            int r0 = wm * 32 + mt * 16 + g;
            a[mt][0] = *(const uint32_t*)&Ah[r0 * EKS + kb];
            a[mt][1] = *(const uint32_t*)&Ah[(r0 + 8) * EKS + kb];
            a[mt][2] = *(const uint32_t*)&Ah[r0 * EKS + kb + 8];
            a[mt][3] = *(const uint32_t*)&Ah[(r0 + 8) * EKS + kb + 8];
        }
        uint32_t b[8][2];
#pragma unroll
        for (int nt = 0; nt < 8; nt++) {
            int col = wn * 64 + nt * 8 + g;
            b[nt][0] = *(const uint32_t*)&Bs[col * EKS + kb];
            b[nt][1] = *(const uint32_t*)&Bs[col * EKS + kb + 8];
        }
#pragma unroll
        for (int mt = 0; mt < 2; mt++)
#pragma unroll
            for (int nt = 0; nt < 8; nt++) {
                float* cc = c[mt][nt];
                asm volatile(
                    "mma.sync.aligned.m16n8k16.row.col.f32.f16.f16.f32 "
                    "{%0,%1,%2,%3}, {%4,%5,%6,%7}, {%8,%9}, {%0,%1,%2,%3};"
                    : "+f"(cc[0]), "+f"(cc[1]), "+f"(cc[2]), "+f"(cc[3])
                    : "r"(a[mt][0]), "r"(a[mt][1]), "r"(a[mt][2]), "r"(a[mt][3]),
                      "r"(b[nt][0]), "r"(b[nt][1]));
            }
    }

#pragma unroll
    for (int mt = 0; mt < 2; mt++) {
        int lr0 = wm * 32 + mt * 16 + g;
        int lr1 = lr0 + 8;
#pragma unroll
        for (int nt = 0; nt < 8; nt++) {
            int colLoc = wn * 64 + nt * 8 + tc * 2;
            float* cc = c[mt][nt];
            float b0 = b2[t * HID + colLoc], b1v = b2[t * HID + colLoc + 1];
            if (start + lr0 < cnt)
                *(__half2*)&g_xh[(size_t)nl[lr0] * HID + colLoc] =
                    __floats2half2_rn(cc[0] + b0, cc[1] + b1v);
            if (start + lr1 < cnt)
                *(__half2*)&g_xh[(size_t)nl[lr1] * HID + colLoc] =
                    __floats2half2_rn(cc[2] + b0, cc[3] + b1v);
        }
    }
}

// ---------------- fp16 mma GEMM: LDSM fragments + cp.async double-buffered B ----------------
#define KS 136
#define AB (128 * KS)                    // halfs per tile
#define MMA_SMEM ((AB + 2 * AB) * 2)     // A + 2 B buffers (bytes) = 104448

__global__ void __launch_bounds__(256, 2)
k_mma(int l, const float* __restrict__ linb) {
    extern __shared__ __half smh[];
    int tid = threadIdx.x;
    int wid = tid >> 5, lane = tid & 31;
    int rowBase = blockIdx.x * 128;
    uint32_t sbase = (uint32_t)__cvta_generic_to_shared(smh);

    // prologue: cp.async A + B chunk 0 (group 0)
    for (int i = tid; i < 2048; i += 256) {
        int row = i >> 4, kc = (i & 15) * 8;
        cpa16(sbase + (row * KS + kc) * 2, &g_xh[(size_t)(rowBase + row) * 128 + kc]);
    }
    const __half* gB = g_Bw + (size_t)l * 512 * 128;
    for (int i = tid; i < 2048; i += 256) {
        int row = i >> 4, kc = (i & 15) * 8;
        cpa16(sbase + (AB + row * KS + kc) * 2, gB + (size_t)row * 128 + kc);
    }
    asm volatile("cp.async.commit_group;" ::: "memory");

    int wm = wid >> 1, wn = wid & 1;
    int sel = lane >> 3, lr = lane & 7;
    int g = lane >> 2, tc = lane & 3;

    // ldmatrix per-lane base addresses
    int arow = wm * 32 + lr + ((sel & 1) << 3);      // +mt*16 later
    int acol = (sel & 2) << 2;                       // 0 or 8 halfs
    uint32_t aAddr = sbase + (arow * KS + acol) * 2;
    int brow = wn * 64 + lr + ((sel & 2) << 2);      // +ntp*16 later
    int bcol = (sel & 1) << 3;
    uint32_t bOff = (brow * KS + bcol) * 2;

    for (int jt = 0; jt < 4; jt++) {
        asm volatile("cp.async.wait_group 0;" ::: "memory");
        __syncthreads();
        if (jt < 3) {   // prefetch next B chunk into other buffer (overlaps compute)
            const __half* gBn = gB + (size_t)(jt + 1) * 128 * 128;
            int bufn = (jt + 1) & 1;
            for (int i = tid; i < 2048; i += 256) {
                int row = i >> 4, kc = (i & 15) * 8;
                cpa16(sbase + (AB + bufn * AB + row * KS + kc) * 2,
                      gBn + (size_t)row * 128 + kc);
            }
            asm volatile("cp.async.commit_group;" ::: "memory");
        }
        uint32_t bAddr = sbase + (AB + (jt & 1) * AB) * 2 + bOff;

        float c[2][8][4];
#pragma unroll
        for (int mt = 0; mt < 2; mt++)
#pragma unroll
            for (int nt = 0; nt < 8; nt++)
#pragma unroll
                for (int q = 0; q < 4; q++) c[mt][nt][q] = 0.f;

#pragma unroll
        for (int k0 = 0; k0 < 8; k0++) {
            uint32_t a[2][4];
            ldsm4(a[0], aAddr + k0 * 32);
            ldsm4(a[1], aAddr + 16 * KS * 2 + k0 * 32);
            uint32_t b[4][4];
#pragma unroll
            for (int ntp = 0; ntp < 4; ntp++)
                ldsm4(b[ntp], bAddr + ntp * 16 * KS * 2 + k0 * 32);
#pragma unroll
            for (int mt = 0; mt < 2; mt++)
#pragma unroll
                for (int ntp = 0; ntp < 4; ntp++) {
                    float* c0 = c[mt][ntp * 2];
                    float* c1 = c[mt][ntp * 2 + 1];
                    asm volatile(
                        "mma.sync.aligned.m16n8k16.row.col.f32.f16.f16.f32 "
                        "{%0,%1,%2,%3}, {%4,%5,%6,%7}, {%8,%9}, {%0,%1,%2,%3};"
                        : "+f"(c0[0]), "+f"(c0[1]), "+f"(c0[2]), "+f"(c0[3])
                        : "r"(a[mt][0]), "r"(a[mt][1]), "r"(a[mt][2]), "r"(a[mt][3]),
                          "r"(b[ntp][0]), "r"(b[ntp][1]));
                    asm volatile(
                        "mma.sync.aligned.m16n8k16.row.col.f32.f16.f16.f32 "
                        "{%0,%1,%2,%3}, {%4,%5,%6,%7}, {%8,%9}, {%0,%1,%2,%3};"
                        : "+f"(c1[0]), "+f"(c1[1]), "+f"(c1[2]), "+f"(c1[3])
                        : "r"(a[mt][0]), "r"(a[mt][1]), "r"(a[mt][2]), "r"(a[mt][3]),
                          "r"(b[ntp][2]), "r"(b[ntp][3]));
                }
        }

#pragma unroll
        for (int mt = 0; mt < 2; mt++) {
            int row0 = rowBase + wm * 32 + mt * 16 + g;
            int row1 = row0 + 8;
#pragma unroll
            for (int nt = 0; nt < 8; nt++) {
                int colLoc = wn * 64 + nt * 8 + tc * 2;
                float* cc = c[mt][nt];
                if (jt < 3) {
                    size_t o0 = (size_t)row0 * 384 + jt * 128 + colLoc;
                    size_t o1 = (size_t)row1 * 384 + jt * 128 + colLoc;
                    if (row0 < NN) *(__half2*)&g_yh[o0] = __floats2half2_rn(cc[0], cc[1]);
                    if (row1 < NN) *(__half2*)&g_yh[o1] = __floats2half2_rn(cc[2], cc[3]);
                } else {
                    float b0 = linb[colLoc], b1 = linb[colLoc + 1];
                    if (row0 < NN)
                        *(float2*)&g_h[(size_t)row0 * 128 + colLoc] = make_float2(cc[0] + b0, cc[1] + b1);
                    if (row1 < NN)
                        *(float2*)&g_h[(size_t)row1 * 128 + colLoc] = make_float2(cc[2] + b0, cc[3] + b1);
                }
            }
        }
        __syncthreads();
    }
}

// ---------------- fused CSR aggregation + LayerNorm ----------------
__global__ void __launch_bounds__(256)
k_aggr_ln(const float* __restrict__ gg, const float* __restrict__ gb, int mode) {
    __shared__ float shp[8][128];
    int warp = threadIdx.x >> 5, lane = threadIdx.x & 31;
    int node = blockIdx.x * 8 + warp;
    bool live = node < NN;
    float4 o = make_float4(0.f, 0.f, 0.f, 0.f);
    int c = lane * 4;

    if (live) {
        int base = g_roff[node];
        int cnt  = g_cnt[node];

        float a0 = 0.f, a1 = 0.f, a2 = 0.f, a3 = 0.f;
        for (int j0 = 0; j0 < cnt; j0 += 8) {
            int v[8];
            uint2 u[8];
#pragma unroll
            for (int q = 0; q < 8; q++)
                v[q] = (j0 + q < cnt) ? __ldg(&g_csr[base + j0 + q]) : -1;
#pragma unroll
            for (int q = 0; q < 8; q++) {
                if (v[q] >= 0) {
                    int s = v[q] >> 2, r = v[q] & 3;
                    u[q] = *(const uint2*)&g_yh[((size_t)s * NREL + r) * HID + c];
                } else {
                    u[q] = make_uint2(0u, 0u);
                }
            }
#pragma unroll
            for (int q = 0; q < 8; q++) {
                float2 f0 = __half22float2(*(__half2*)&u[q].x);
                float2 f1 = __half22float2(*(__half2*)&u[q].y);
                a0 += f0.x; a1 += f0.y; a2 += f1.x; a3 += f1.y;
            }
        }
        float di = 1.0f / fmaxf((float)cnt, 1.0f);

        float4 hv = *(const float4*)&g_h[(size_t)node * HID + c];
        hv.x += a0 * di; hv.y += a1 * di; hv.z += a2 * di; hv.w += a3 * di;

        float s = hv.x + hv.y + hv.z + hv.w;
#pragma unroll
        for (int of = 16; of; of >>= 1) s += __shfl_xor_sync(0xFFFFFFFFu, s, of);
        float mu = s * (1.0f / HID);
        float dx = hv.x - mu, dy = hv.y - mu, dz = hv.z - mu, dw = hv.w - mu;
        float s2 = dx * dx + dy * dy + dz * dz + dw * dw;
#pragma unroll
        for (int of = 16; of; of >>= 1) s2 += __shfl_xor_sync(0xFFFFFFFFu, s2, of);
        float rs = rsqrtf(s2 * (1.0f / HID) + LN_EPS);

        float4 g4 = *(const float4*)&gg[c];
        float4 b4 = *(const float4*)&gb[c];
        o = make_float4(dx * rs * g4.x + b4.x, dy * rs * g4.y + b4.y,
                        dz * rs * g4.z + b4.z, dw * rs * g4.w + b4.w);
    }

    if (mode == 0) {
        if (live) {
            __half2 h0 = __floats2half2_rn(o.x, o.y);
            __half2 h1 = __floats2half2_rn(o.z, o.w);
            *(float2*)&g_xh[(size_t)node * HID + c] =
                make_float2(__uint_as_float(*(uint32_t*)&h0), __uint_as_float(*(uint32_t*)&h1));
        }
    } else {
        shp[warp][c]     = o.x;
        shp[warp][c + 1] = o.y;
        shp[warp][c + 2] = o.z;
        shp[warp][c + 3] = o.w;
        __syncthreads();
        if (threadIdx.x < 128) {
            float s = 0.f;
#pragma unroll
            for (int w = 0; w < 8; w++) s += shp[w][threadIdx.x];
            atomicAdd(&g_pool[threadIdx.x], s);
        }
    }
}

// ---------------- regressor ----------------
__global__ void k_final(const float* __restrict__ regW, const float* __restrict__ regb,
                        float* __restrict__ out) {
    int c = threadIdx.x;
    __shared__ float red[HID];
    red[c] = g_pool[c] * (1.0f / NN) * regW[c];
    __syncthreads();
    for (int s = 64; s; s >>= 1) {
        if (c < s) red[c] += red[c + s];
        __syncthreads();
    }
    if (c == 0) out[0] = red[0] + regb[0];
}

// ---------------- launch ----------------
extern "C" void kernel_launch(void* const* d_in, const int* in_sizes, int n_in,
                              void* d_out, int out_size) {
    const int*   z     = (const int*)d_in[0];
    const float* sd    = (const float*)d_in[1];
    const float* dfp   = (const float*)d_in[2];
    const float* cond  = (const float*)d_in[3];
    const float* mult  = (const float*)d_in[4];
    const int*   ntype = (const int*)d_in[5];
    const int*   eidx  = (const int*)d_in[6];
    const int*   etyp  = (const int*)d_in[7];
    const float* zemb  = (const float*)d_in[8];
    const float* eW1   = (const float*)d_in[9];
    const float* eb1   = (const float*)d_in[10];
    const float* eW2   = (const float*)d_in[11];
    const float* eb2   = (const float*)d_in[12];
    const float* linW  = (const float*)d_in[13];
    const float* linb  = (const float*)d_in[14];
    const float* relW  = (const float*)d_in[15];
    const float* lng   = (const float*)d_in[16];
    const float* lnb   = (const float*)d_in[17];
    const float* regW  = (const float*)d_in[18];
    const float* regb  = (const float*)d_in[19];
    float* out = (float*)d_out;

    cudaFuncSetAttribute(k_encoder, cudaFuncAttributeMaxDynamicSharedMemorySize, ENC_SMEM);
    cudaFuncSetAttribute(k_mma, cudaFuncAttributeMaxDynamicSharedMemorySize, MMA_SMEM);

    const int rowBlocks = NPAD / 128;   // 782

    // order chosen so launch #4 (ncu capture) is k_mma layer 0
    k_prepB<<<512, 256>>>(relW, linW);                       // 1 (also clears tcount)
    k_bucket<<<(NN + 255) / 256, 256>>>(ntype);              // 2
    k_encoder<<<dim3(rowBlocks, NTYPE), 256, ENC_SMEM>>>(    // 3
        z, sd, dfp, cond, mult, zemb, eW1, eb1, eW2, eb2);
    k_mma<<<rowBlocks, 256, MMA_SMEM>>>(0, linb);            // 4  <-- ncu
    k_init2<<<(NN + 255) / 256, 256>>>();                    // 5
    k_cnt<<<(EE + 255) / 256, 256>>>(eidx + EE);             // 6
    k_scan1<<<(NN + 255) / 256, 256>>>();                    // 7
    k_scan2<<<1, 512>>>();                                   // 8
    k_scan3<<<(NN + 255) / 256, 256>>>();                    // 9
    k_fill<<<(EE + 255) / 256, 256>>>(eidx, eidx + EE, etyp);// 10
    k_aggr_ln<<<(NN + 7) / 8, 256>>>(lng, lnb, 0);           // 11
    k_mma<<<rowBlocks, 256, MMA_SMEM>>>(1, linb + HID);      // 12
    k_aggr_ln<<<(NN + 7) / 8, 256>>>(lng + HID, lnb + HID, 1); // 13
    k_final<<<1, 128>>>(regW, regb, out);                    // 14
}